// round 7
// baseline (speedup 1.0000x reference)
#include <cuda_runtime.h>
#include <cuda_bf16.h>
#include <cstdint>
#include <math.h>

// Problem constants
#define BB 2
#define SS 2048
#define HH 16
#define DD 128
#define NSTATE 2048
#define QKV_W (3*HH*DD)   // 6144

// ---------------- scratch (device globals; no runtime alloc) ----------------
__device__ float g_qkv[(size_t)BB * SS * QKV_W];    // [B,S,6144]
__device__ float g_attn[(size_t)BB * SS * HH * DD]; // [B,S,H,D]
__device__ float g_xr[(size_t)BB * SS * NSTATE];    // x rounded to tf32
__device__ float g_wq[(size_t)QKV_W * NSTATE];      // W_qkv rounded
__device__ float g_wo[(size_t)NSTATE * NSTATE];     // W_o rounded

// ---------------- helpers ----------------------------------------------------
__device__ __forceinline__ uint32_t tf32_rna(float x) {
    uint32_t r; asm("cvt.rna.tf32.f32 %0, %1;" : "=r"(r) : "f"(x)); return r;
}
__device__ __forceinline__ uint32_t smem_u32(const void* p) {
    uint32_t a;
    asm("{ .reg .u64 t; cvta.to.shared.u64 t, %1; cvt.u32.u64 %0, t; }"
        : "=r"(a) : "l"(p));
    return a;
}
__device__ __forceinline__ void mma_tf32_16x8x8(float* c, const uint32_t* a,
                                                const uint32_t* b) {
    asm volatile(
        "mma.sync.aligned.m16n8k8.row.col.f32.tf32.tf32.f32 "
        "{%0,%1,%2,%3}, {%4,%5,%6,%7}, {%8,%9}, {%0,%1,%2,%3};\n"
        : "+f"(c[0]), "+f"(c[1]), "+f"(c[2]), "+f"(c[3])
        : "r"(a[0]), "r"(a[1]), "r"(a[2]), "r"(a[3]), "r"(b[0]), "r"(b[1]));
}
__device__ __forceinline__ void ldsm_x4(uint32_t* r, uint32_t addr) {
    asm volatile("ldmatrix.sync.aligned.m8n8.x4.shared.b16 {%0,%1,%2,%3}, [%4];"
                 : "=r"(r[0]), "=r"(r[1]), "=r"(r[2]), "=r"(r[3]) : "r"(addr));
}
__device__ __forceinline__ void cp16(uint32_t s, const void* g) {
    asm volatile("cp.async.cg.shared.global [%0], [%1], 16;"
                 :: "r"(s), "l"(g) : "memory");
}
#define CP_COMMIT() asm volatile("cp.async.commit_group;" ::: "memory")
#define CP_WAIT1()  asm volatile("cp.async.wait_group 1;"  ::: "memory")

// ---------------- tf32 pre-round pass ---------------------------------------
__global__ void round_tf32(const float* __restrict__ src,
                           float* __restrict__ dst, int n4) {
    int i = blockIdx.x * blockDim.x + threadIdx.x;
    if (i >= n4) return;
    float4 v = ((const float4*)src)[i];
    uint4 r = { tf32_rna(v.x), tf32_rna(v.y), tf32_rna(v.z), tf32_rna(v.w) };
    ((uint4*)dst)[i] = r;
}

// ============================================================================
// tf32 mma.sync GEMM (NT): C[m,n] = sum_k A[m,k]*B[n,k] (+bias[n])
// A, B pre-rounded to tf32. Block 128x256x16, 8 warps (2x4), warp tile 64x64,
// 3-stage cp.async pipeline, TPAD=20, ldmatrix fragments.
// ============================================================================
#define TPAD 20
#define G_BM 128
#define G_BN 256
#define G_NSTG 3
#define G_ABYTES (G_BM * TPAD * 4)            // 10240
#define G_BBYTES (G_BN * TPAD * 4)            // 20480
#define G_STG (G_ABYTES + G_BBYTES)           // 30720
#define G_SMEM (G_NSTG * G_STG)               // 92160

__device__ __forceinline__ void gemm_issue(uint32_t sbase,
                                           const float* __restrict__ A,
                                           const float* __restrict__ B,
                                           int m0, int n0, int K, int k0,
                                           int tid) {
    const uint32_t sA = sbase, sB = sbase + G_ABYTES;
#pragma unroll
    for (int j = 0; j < 2; j++) {
        int ca = tid + j * 256;                 // 512 16B chunks of A
        int row = ca >> 2, cc = ca & 3;
        cp16(sA + (uint32_t)(row * TPAD + cc * 4) * 4,
             &A[(size_t)(m0 + row) * K + k0 + cc * 4]);
    }
#pragma unroll
    for (int j = 0; j < 4; j++) {
        int cb = tid + j * 256;                 // 1024 16B chunks of B
        int row = cb >> 2, cc = cb & 3;
        cp16(sB + (uint32_t)(row * TPAD + cc * 4) * 4,
             &B[(size_t)(n0 + row) * K + k0 + cc * 4]);
    }
}

__global__ __launch_bounds__(256, 1)
void gemm_mma(const float* __restrict__ A, const float* __restrict__ B,
              const float* __restrict__ bias, float* __restrict__ C,
              int M, int N, int K) {
    extern __shared__ uint32_t dynsm[];
    const uint32_t sb = smem_u32(dynsm);

    const int tid = threadIdx.x;
    const int w = tid >> 5, l = tid & 31;
    const int lr = l >> 2, lc = l & 3;
    const int wm = w >> 2, wn = w & 3;           // 2 (m) x 4 (n)
    const int m0 = blockIdx.y * G_BM, n0 = blockIdx.x * G_BN;
    const int mat = l >> 3;

    // per-lane ldmatrix fragment bases (within a stage)
    const uint32_t aOff = (uint32_t)(((wm * 64 + (mat & 1) * 8 + (l & 7)) * TPAD)
                                     + (mat >> 1) * 4) * 4;
    const uint32_t bOff = G_ABYTES
                        + (uint32_t)(((wn * 64 + (mat >> 1) * 8 + (l & 7)) * TPAD)
                                     + (mat & 1) * 4) * 4;

    float acc[4][8][4];
#pragma unroll
    for (int mt = 0; mt < 4; mt++)
#pragma unroll
        for (int nt = 0; nt < 8; nt++)
#pragma unroll
            for (int i = 0; i < 4; i++) acc[mt][nt][i] = 0.f;

    const int NC = K / 16;

    // prologue: issue stages 0..NSTG-2
#pragma unroll
    for (int s = 0; s < G_NSTG - 1; s++) {
        gemm_issue(sb + s * G_STG, A, B, m0, n0, K, s * 16, tid);
        CP_COMMIT();
    }

    for (int c = 0; c < NC; c++) {
        CP_WAIT1();
        __syncthreads();

        const int nc = c + G_NSTG - 1;
        if (nc < NC)
            gemm_issue(sb + (nc % G_NSTG) * G_STG, A, B, m0, n0, K, nc * 16, tid);
        CP_COMMIT();                              // empty group at tail is fine

        const uint32_t st = sb + (c % G_NSTG) * G_STG;
#pragma unroll
        for (int kk = 0; kk < 2; kk++) {
            uint32_t af[4][4];
#pragma unroll
            for (int mt = 0; mt < 4; mt++)
                ldsm_x4(af[mt], st + aOff + kk * 32 + mt * (16 * TPAD * 4));
#pragma unroll
            for (int p = 0; p < 4; p++) {
                uint32_t r[4];
                ldsm_x4(r, st + bOff + kk * 32 + p * (16 * TPAD * 4));
#pragma unroll
                for (int mt = 0; mt < 4; mt++) {
                    mma_tf32_16x8x8(acc[mt][2 * p], af[mt], r);
                    mma_tf32_16x8x8(acc[mt][2 * p + 1], af[mt], r + 2);
                }
            }
        }
        __syncthreads();
    }

    // epilogue
#pragma unroll
    for (int mt = 0; mt < 4; mt++) {
        int m = m0 + wm * 64 + mt * 16 + lr;
#pragma unroll
        for (int nt = 0; nt < 8; nt++) {
            int n = n0 + wn * 64 + nt * 8 + lc * 2;
            float bx = 0.f, by = 0.f;
            if (bias) { bx = bias[n]; by = bias[n + 1]; }
            float2 v0 = { acc[mt][nt][0] + bx, acc[mt][nt][1] + by };
            float2 v1 = { acc[mt][nt][2] + bx, acc[mt][nt][3] + by };
            *(float2*)&C[(size_t)m * N + n] = v0;
            *(float2*)&C[(size_t)(m + 8) * N + n] = v1;
        }
    }
}

// ---------------- RoPE (q in place, k -> out_k), v copy ---------------------
__global__ void rope_scatter(float* __restrict__ qkv,
                             const float* __restrict__ f_r,
                             const float* __restrict__ f_i,
                             float* __restrict__ out_k,
                             float* __restrict__ out_v) {
    int idx = blockIdx.x * blockDim.x + threadIdx.x;
    if (idx >= BB * SS * HH * 64) return;
    int d2 = idx & 63;
    int h  = (idx >> 6) & (HH - 1);
    int bs = idx >> 10;

    float fr = f_r[(size_t)bs * 64 + d2];
    float fi = f_i[(size_t)bs * 64 + d2];

    size_t base = (size_t)bs * QKV_W;
    size_t qi = base + (size_t)h * DD + d2;
    float xr = qkv[qi], xi = qkv[qi + 64];
    qkv[qi]      = xr * fr - xi * fi;
    qkv[qi + 64] = xr * fi + xi * fr;

    size_t ki = base + (size_t)HH * DD + (size_t)h * DD + d2;
    xr = qkv[ki]; xi = qkv[ki + 64];
    size_t ko = ((size_t)bs * HH + h) * DD + d2;
    out_k[ko]      = xr * fr - xi * fi;
    out_k[ko + 64] = xr * fi + xi * fr;

    size_t vi = base + (size_t)2 * HH * DD + (size_t)h * DD + d2;
    out_v[ko]      = qkv[vi];
    out_v[ko + 64] = qkv[vi + 64];
}

// ============================================================================
// Flash attention on tf32 mma.sync + ldmatrix. BM=128 (8 warps x 16), BN=64.
// Q,K tf32 smem; V transposed (Vt[d][j]); P per-warp smem. Causal block skip.
// Epilogue writes tf32-rounded output (feeds pre-rounded GEMM2).
// ============================================================================
#define QP 132
#define KP 132
#define VP 68
#define PP 68
#define FA_WORDS (128*QP + 64*KP + 128*VP + 128*PP)
#define FA_BYTES (FA_WORDS * 4)

__global__ __launch_bounds__(256, 1)
void flash_attn(const float* __restrict__ qkv,
                const float* __restrict__ kbuf,
                const float* __restrict__ vbuf,
                const float* __restrict__ mask,
                float* __restrict__ attn_out) {
    extern __shared__ uint32_t smw[];
    uint32_t* Qs = smw;                 // [128][QP] tf32
    uint32_t* Ks = Qs + 128 * QP;       // [64][KP]
    uint32_t* Vt = Ks + 64 * KP;        // [128][VP] (V transposed: [d][j])
    uint32_t* Ps = Vt + 128 * VP;       // [128][PP]

    const int qb = blockIdx.x, h = blockIdx.y, b = blockIdx.z;
    const int tid = threadIdx.x, w = tid >> 5, l = tid & 31;
    const int lr = l >> 2, lc = l & 3;
    const float scale = 0.08838834764831845f;   // 1/sqrt(128)

    const int mat = l >> 3;
    const uint32_t sQ = smem_u32(Qs), sK = smem_u32(Ks);
    const uint32_t sV = smem_u32(Vt), sP = smem_u32(Ps);
    const uint32_t qFrag = sQ + (uint32_t)(((w * 16 + (mat & 1) * 8 + (l & 7)) * QP)
                                           + (mat >> 1) * 4) * 4;
    const uint32_t kFrag = sK + (uint32_t)((((mat >> 1) * 8 + (l & 7)) * KP)
                                           + (mat & 1) * 4) * 4;
    const uint32_t vFrag = sV + (uint32_t)((((mat >> 1) * 8 + (l & 7)) * VP)
                                           + (mat & 1) * 4) * 4;
    const uint32_t pFrag = sP + (uint32_t)(((w * 16 + (mat & 1) * 8 + (l & 7)) * PP)
                                           + (mat >> 1) * 4) * 4;

    for (int t = tid; t < 128 * 32; t += 256) {
        int r = t >> 5, c4 = (t & 31) * 4;
        float4 v = *(const float4*)&qkv[((size_t)b * SS + qb * 128 + r) * QKV_W
                                        + h * DD + c4];
        uint32_t* dst = &Qs[r * QP + c4];
        dst[0] = tf32_rna(v.x * scale); dst[1] = tf32_rna(v.y * scale);
        dst[2] = tf32_rna(v.z * scale); dst[3] = tf32_rna(v.w * scale);
    }

    float O[16][4];
#pragma unroll
    for (int nt = 0; nt < 16; nt++)
#pragma unroll
        for (int i = 0; i < 4; i++) O[nt][i] = 0.f;
    float m_lo = -INFINITY, m_hi = -INFINITY, l_lo = 0.f, l_hi = 0.f;

    const int aP = (w * 16 + lr) * PP;
    const int nKV = 2 * qb + 2;

    for (int kb = 0; kb < nKV; kb++) {
        __syncthreads();
        for (int t = tid; t < 64 * 32; t += 256) {
            int r = t >> 5, c4 = (t & 31) * 4;
            size_t src = ((size_t)b * SS + kb * 64 + r) * (HH * DD)
                       + (size_t)h * DD + c4;
            float4 kv = *(const float4*)&kbuf[src];
            uint32_t* kd = &Ks[r * KP + c4];
            kd[0] = tf32_rna(kv.x); kd[1] = tf32_rna(kv.y);
            kd[2] = tf32_rna(kv.z); kd[3] = tf32_rna(kv.w);
            float4 vv = *(const float4*)&vbuf[src];
            Vt[(c4 + 0) * VP + r] = tf32_rna(vv.x);
            Vt[(c4 + 1) * VP + r] = tf32_rna(vv.y);
            Vt[(c4 + 2) * VP + r] = tf32_rna(vv.z);
            Vt[(c4 + 3) * VP + r] = tf32_rna(vv.w);
        }
        __syncthreads();

        float S[8][4];
#pragma unroll
        for (int nt = 0; nt < 8; nt++)
#pragma unroll
            for (int i = 0; i < 4; i++) S[nt][i] = 0.f;
#pragma unroll
        for (int ks = 0; ks < 16; ks++) {
            uint32_t af[4];
            ldsm_x4(af, qFrag + ks * 32);
#pragma unroll
            for (int p = 0; p < 4; p++) {
                uint32_t r[4];
                ldsm_x4(r, kFrag + ks * 32 + p * (16 * KP * 4));
                mma_tf32_16x8x8(S[2 * p], af, r);
                mma_tf32_16x8x8(S[2 * p + 1], af, r + 2);
            }
        }

        if (kb >= 2 * qb) {
            const int m_glo = qb * 128 + w * 16 + lr;
            const float* mr0 = &mask[((size_t)b * SS + m_glo) * SS + kb * 64];
            const float* mr1 = mr0 + 8 * SS;
#pragma unroll
            for (int nt = 0; nt < 8; nt++) {
                float2 q0 = *(const float2*)&mr0[nt * 8 + lc * 2];
                float2 q1 = *(const float2*)&mr1[nt * 8 + lc * 2];
                S[nt][0] += q0.x; S[nt][1] += q0.y;
                S[nt][2] += q1.x; S[nt][3] += q1.y;
            }
        }

        float bm_lo = -INFINITY, bm_hi = -INFINITY;
#pragma unroll
        for (int nt = 0; nt < 8; nt++) {
            bm_lo = fmaxf(bm_lo, fmaxf(S[nt][0], S[nt][1]));
            bm_hi = fmaxf(bm_hi, fmaxf(S[nt][2], S[nt][3]));
        }
        bm_lo = fmaxf(bm_lo, __shfl_xor_sync(0xffffffff, bm_lo, 1));
        bm_lo = fmaxf(bm_lo, __shfl_xor_sync(0xffffffff, bm_lo, 2));
        bm_hi = fmaxf(bm_hi, __shfl_xor_sync(0xffffffff, bm_hi, 1));
        bm_hi = fmaxf(bm_hi, __shfl_xor_sync(0xffffffff, bm_hi, 2));
        float mn_lo = fmaxf(m_lo, bm_lo);
        float mn_hi = fmaxf(m_hi, bm_hi);

        float rs_lo = 0.f, rs_hi = 0.f;
#pragma unroll
        for (int nt = 0; nt < 8; nt++) {
            S[nt][0] = __expf(S[nt][0] - mn_lo);
            S[nt][1] = __expf(S[nt][1] - mn_lo);
            S[nt][2] = __expf(S[nt][2] - mn_hi);
            S[nt][3] = __expf(S[nt][3] - mn_hi);
            rs_lo += S[nt][0] + S[nt][1];
            rs_hi += S[nt][2] + S[nt][3];
        }
        rs_lo += __shfl_xor_sync(0xffffffff, rs_lo, 1);
        rs_lo += __shfl_xor_sync(0xffffffff, rs_lo, 2);
        rs_hi += __shfl_xor_sync(0xffffffff, rs_hi, 1);
        rs_hi += __shfl_xor_sync(0xffffffff, rs_hi, 2);

        float al_lo = __expf(m_lo - mn_lo);
        float al_hi = __expf(m_hi - mn_hi);
        l_lo = l_lo * al_lo + rs_lo;
        l_hi = l_hi * al_hi + rs_hi;
        m_lo = mn_lo; m_hi = mn_hi;
#pragma unroll
        for (int nt = 0; nt < 16; nt++) {
            O[nt][0] *= al_lo; O[nt][1] *= al_lo;
            O[nt][2] *= al_hi; O[nt][3] *= al_hi;
        }

#pragma unroll
        for (int nt = 0; nt < 8; nt++) {
            int cw = nt * 8 + lc * 2;
            uint2 p0 = { tf32_rna(S[nt][0]), tf32_rna(S[nt][1]) };
            uint2 p1 = { tf32_rna(S[nt][2]), tf32_rna(S[nt][3]) };
            *(uint2*)&Ps[aP + cw] = p0;
            *(uint2*)&Ps[aP + 8 * PP + cw] = p1;
        }
        __syncwarp();

#pragma unroll
        for (int ks = 0; ks < 8; ks++) {
            uint32_t af[4];
            ldsm_x4(af, pFrag + ks * 32);
#pragma unroll
            for (int p = 0; p < 8; p++) {
                uint32_t r[4];
                ldsm_x4(r, vFrag + ks * 32 + p * (16 * VP * 4));
                mma_tf32_16x8x8(O[2 * p], af, r);
                mma_tf32_16x8x8(O[2 * p + 1], af, r + 2);
            }
        }
        __syncwarp();
    }

    // epilogue: normalize, round to tf32 (GEMM2 input), write [B,S,H,D]
    const float inv_lo = 1.0f / l_lo, inv_hi = 1.0f / l_hi;
    const int m0 = qb * 128 + w * 16 + lr;
#pragma unroll
    for (int nt = 0; nt < 16; nt++) {
        int d = nt * 8 + lc * 2;
        uint2 v0 = { tf32_rna(O[nt][0] * inv_lo), tf32_rna(O[nt][1] * inv_lo) };
        uint2 v1 = { tf32_rna(O[nt][2] * inv_hi), tf32_rna(O[nt][3] * inv_hi) };
        *(uint2*)&attn_out[(((size_t)b * SS + m0) * HH + h) * DD + d] = v0;
        *(uint2*)&attn_out[(((size_t)b * SS + m0 + 8) * HH + h) * DD + d] = v1;
    }
}

// ---------------- launch ----------------------------------------------------
extern "C" void kernel_launch(void* const* d_in, const int* in_sizes, int n_in,
                              void* d_out, int out_size) {
    const float* x      = (const float*)d_in[0];
    const float* f_r    = (const float*)d_in[1];
    const float* f_i    = (const float*)d_in[2];
    const float* mask   = (const float*)d_in[3];
    const float* W_qkv  = (const float*)d_in[4];
    const float* b_qkv  = (const float*)d_in[5];
    const float* W_o    = (const float*)d_in[6];

    float* out   = (float*)d_out;
    float* out_k = out   + (size_t)BB * SS * NSTATE;
    float* out_v = out_k + (size_t)BB * SS * HH * DD;

    float* qkv = nullptr;  cudaGetSymbolAddress((void**)&qkv,  g_qkv);
    float* attn = nullptr; cudaGetSymbolAddress((void**)&attn, g_attn);
    float* xr = nullptr;   cudaGetSymbolAddress((void**)&xr,   g_xr);
    float* wq = nullptr;   cudaGetSymbolAddress((void**)&wq,   g_wq);
    float* wo = nullptr;   cudaGetSymbolAddress((void**)&wo,   g_wo);

    const int M = BB * SS;   // 4096

    cudaFuncSetAttribute(gemm_mma, cudaFuncAttributeMaxDynamicSharedMemorySize,
                         G_SMEM);
    cudaFuncSetAttribute(flash_attn, cudaFuncAttributeMaxDynamicSharedMemorySize,
                         FA_BYTES);

    // 0) pre-round inputs to tf32
    {
        int n4x = (M * NSTATE) / 4;
        round_tf32<<<(n4x + 255) / 256, 256>>>(x, xr, n4x);
        int n4q = (QKV_W * NSTATE) / 4;
        round_tf32<<<(n4q + 255) / 256, 256>>>(W_qkv, wq, n4q);
        int n4o = (NSTATE * NSTATE) / 4;
        round_tf32<<<(n4o + 255) / 256, 256>>>(W_o, wo, n4o);
    }

    // 1) QKV projection (tf32 mma.sync, cp.async pipeline)
    gemm_mma<<<dim3(QKV_W / G_BN, M / G_BM), 256, G_SMEM>>>(
        xr, wq, b_qkv, qkv, M, QKV_W, NSTATE);
    // 2) RoPE q,k; scatter k,v to output
    rope_scatter<<<(BB * SS * HH * 64) / 256, 256>>>(qkv, f_r, f_i, out_k, out_v);
    // 3) attention (tf32 mma + ldmatrix, causal block skip)
    flash_attn<<<dim3(SS / 128, HH, BB), 256, FA_BYTES>>>(qkv, out_k, out_v,
                                                          mask, attn);
    // 4) output projection (tf32 mma.sync, cp.async pipeline)
    gemm_mma<<<dim3(NSTATE / G_BN, M / G_BM), 256, G_SMEM>>>(
        attn, wo, nullptr, out, M, NSTATE, NSTATE);
}

// round 8
// speedup vs baseline: 1.1499x; 1.1499x over previous
#include <cuda_runtime.h>
#include <cuda_bf16.h>
#include <cstdint>
#include <math.h>

// Problem constants
#define BB 2
#define SS 2048
#define HH 16
#define DD 128
#define NSTATE 2048
#define QKV_W (3*HH*DD)   // 6144

// ---------------- scratch (device globals; no runtime alloc) ----------------
__device__ float g_qkv[(size_t)BB * SS * QKV_W];    // [B,S,6144]
__device__ float g_attn[(size_t)BB * SS * HH * DD]; // [B,S,H,D]
__device__ float g_xr[(size_t)BB * SS * NSTATE];    // x rounded to tf32
__device__ float g_wq[(size_t)QKV_W * NSTATE];      // W_qkv rounded
__device__ float g_wo[(size_t)NSTATE * NSTATE];     // W_o rounded
__device__ uint32_t g_kr[(size_t)BB * HH * SS * DD]; // k tf32, [B,H,S,D]
__device__ uint32_t g_vr[(size_t)BB * HH * DD * SS]; // v tf32, [B,H,D,S]

// ---------------- helpers ----------------------------------------------------
__device__ __forceinline__ uint32_t tf32_rna(float x) {
    uint32_t r; asm("cvt.rna.tf32.f32 %0, %1;" : "=r"(r) : "f"(x)); return r;
}
__device__ __forceinline__ uint32_t smem_u32(const void* p) {
    uint32_t a;
    asm("{ .reg .u64 t; cvta.to.shared.u64 t, %1; cvt.u32.u64 %0, t; }"
        : "=r"(a) : "l"(p));
    return a;
}
__device__ __forceinline__ void mma_tf32_16x8x8(float* c, const uint32_t* a,
                                                const uint32_t* b) {
    asm volatile(
        "mma.sync.aligned.m16n8k8.row.col.f32.tf32.tf32.f32 "
        "{%0,%1,%2,%3}, {%4,%5,%6,%7}, {%8,%9}, {%0,%1,%2,%3};\n"
        : "+f"(c[0]), "+f"(c[1]), "+f"(c[2]), "+f"(c[3])
        : "r"(a[0]), "r"(a[1]), "r"(a[2]), "r"(a[3]), "r"(b[0]), "r"(b[1]));
}
__device__ __forceinline__ void ldsm_x4(uint32_t* r, uint32_t addr) {
    asm volatile("ldmatrix.sync.aligned.m8n8.x4.shared.b16 {%0,%1,%2,%3}, [%4];"
                 : "=r"(r[0]), "=r"(r[1]), "=r"(r[2]), "=r"(r[3]) : "r"(addr));
}
__device__ __forceinline__ void cp16(uint32_t s, const void* g) {
    asm volatile("cp.async.cg.shared.global [%0], [%1], 16;"
                 :: "r"(s), "l"(g) : "memory");
}
#define CP_COMMIT() asm volatile("cp.async.commit_group;" ::: "memory")
#define CP_WAIT2()  asm volatile("cp.async.wait_group 2;"  ::: "memory")

// ---------------- tf32 pre-round pass ---------------------------------------
__global__ void round_tf32(const float* __restrict__ src,
                           float* __restrict__ dst, int n4) {
    int i = blockIdx.x * blockDim.x + threadIdx.x;
    if (i >= n4) return;
    float4 v = ((const float4*)src)[i];
    uint4 r = { tf32_rna(v.x), tf32_rna(v.y), tf32_rna(v.z), tf32_rna(v.w) };
    ((uint4*)dst)[i] = r;
}

// ============================================================================
// tf32 mma.sync GEMM (NT): C[m,n] = sum_k A[m,k]*B[n,k] (+bias[n])
// Inputs pre-rounded. Block 128x128x16, 8 warps (4x2), warp tile 32x64,
// 4-stage cp.async ring, TPAD=20, ldmatrix fragments. 2 CTAs/SM.
// ============================================================================
#define TPAD 20
#define G_NSTG 4
#define G_ABYTES (128 * TPAD * 4)             // 10240
#define G_STG (2 * G_ABYTES)                  // 20480 (A + B)
#define G_SMEM (G_NSTG * G_STG)               // 81920

__device__ __forceinline__ void gemm_issue(uint32_t sbase,
                                           const float* __restrict__ A,
                                           const float* __restrict__ B,
                                           int m0, int n0, int K, int k0,
                                           int tid) {
    const int row = tid >> 2, cc = tid & 3;
    cp16(sbase + (uint32_t)(row * TPAD + cc * 4) * 4,
         &A[(size_t)(m0 + row) * K + k0 + cc * 4]);
    cp16(sbase + (uint32_t)((row + 64) * TPAD + cc * 4) * 4,
         &A[(size_t)(m0 + row + 64) * K + k0 + cc * 4]);
    const uint32_t sB = sbase + G_ABYTES;
    cp16(sB + (uint32_t)(row * TPAD + cc * 4) * 4,
         &B[(size_t)(n0 + row) * K + k0 + cc * 4]);
    cp16(sB + (uint32_t)((row + 64) * TPAD + cc * 4) * 4,
         &B[(size_t)(n0 + row + 64) * K + k0 + cc * 4]);
}

__global__ __launch_bounds__(256, 2)
void gemm_mma(const float* __restrict__ A, const float* __restrict__ B,
              const float* __restrict__ bias, float* __restrict__ C,
              int M, int N, int K) {
    extern __shared__ uint32_t dynsm[];
    const uint32_t sb = smem_u32(dynsm);

    const int tid = threadIdx.x;
    const int w = tid >> 5, l = tid & 31;
    const int lr = l >> 2, lc = l & 3;
    const int wm = w >> 1, wn = w & 1;           // 4 (m) x 2 (n)
    const int m0 = blockIdx.y * 128, n0 = blockIdx.x * 128;
    const int mat = l >> 3;

    const uint32_t aOff = (uint32_t)(((wm * 32 + (mat & 1) * 8 + (l & 7)) * TPAD)
                                     + (mat >> 1) * 4) * 4;
    const uint32_t bOff = G_ABYTES
                        + (uint32_t)(((wn * 64 + (mat >> 1) * 8 + (l & 7)) * TPAD)
                                     + (mat & 1) * 4) * 4;

    float acc[2][8][4];
#pragma unroll
    for (int mt = 0; mt < 2; mt++)
#pragma unroll
        for (int nt = 0; nt < 8; nt++)
#pragma unroll
            for (int i = 0; i < 4; i++) acc[mt][nt][i] = 0.f;

    const int NC = K / 16;

#pragma unroll
    for (int s = 0; s < G_NSTG - 1; s++) {
        gemm_issue(sb + s * G_STG, A, B, m0, n0, K, s * 16, tid);
        CP_COMMIT();
    }

    for (int c = 0; c < NC; c++) {
        CP_WAIT2();
        __syncthreads();

        const int nc = c + G_NSTG - 1;
        if (nc < NC)
            gemm_issue(sb + (nc % G_NSTG) * G_STG, A, B, m0, n0, K, nc * 16, tid);
        CP_COMMIT();

        const uint32_t st = sb + (c % G_NSTG) * G_STG;
#pragma unroll
        for (int kk = 0; kk < 2; kk++) {
            uint32_t af[2][4];
            ldsm_x4(af[0], st + aOff + kk * 32);
            ldsm_x4(af[1], st + aOff + kk * 32 + 16 * TPAD * 4);
#pragma unroll
            for (int p = 0; p < 4; p++) {
                uint32_t r[4];
                ldsm_x4(r, st + bOff + kk * 32 + p * (16 * TPAD * 4));
#pragma unroll
                for (int mt = 0; mt < 2; mt++) {
                    mma_tf32_16x8x8(acc[mt][2 * p], af[mt], r);
                    mma_tf32_16x8x8(acc[mt][2 * p + 1], af[mt], r + 2);
                }
            }
        }
        __syncthreads();
    }

#pragma unroll
    for (int mt = 0; mt < 2; mt++) {
        int m = m0 + wm * 32 + mt * 16 + lr;
#pragma unroll
        for (int nt = 0; nt < 8; nt++) {
            int n = n0 + wn * 64 + nt * 8 + lc * 2;
            float bx = 0.f, by = 0.f;
            if (bias) { bx = bias[n]; by = bias[n + 1]; }
            float2 v0 = { acc[mt][nt][0] + bx, acc[mt][nt][1] + by };
            float2 v1 = { acc[mt][nt][2] + bx, acc[mt][nt][3] + by };
            *(float2*)&C[(size_t)m * N + n] = v0;
            *(float2*)&C[(size_t)(m + 8) * N + n] = v1;
        }
    }
}

// ---------------- RoPE: q in place; k -> out_k (fp32) + g_kr (tf32, head-major)
__global__ void rope_scatter(float* __restrict__ qkv,
                             const float* __restrict__ f_r,
                             const float* __restrict__ f_i,
                             float* __restrict__ out_k,
                             float* __restrict__ out_v,
                             uint32_t* __restrict__ kr) {
    int idx = blockIdx.x * blockDim.x + threadIdx.x;
    if (idx >= BB * SS * HH * 64) return;
    int d2 = idx & 63;
    int h  = (idx >> 6) & (HH - 1);
    int bs = idx >> 10;
    int b = bs >> 11, s = bs & (SS - 1);

    float fr = f_r[(size_t)bs * 64 + d2];
    float fi = f_i[(size_t)bs * 64 + d2];

    size_t base = (size_t)bs * QKV_W;
    size_t qi = base + (size_t)h * DD + d2;
    float xr = qkv[qi], xi = qkv[qi + 64];
    qkv[qi]      = xr * fr - xi * fi;
    qkv[qi + 64] = xr * fi + xi * fr;

    size_t ki = base + (size_t)HH * DD + (size_t)h * DD + d2;
    xr = qkv[ki]; xi = qkv[ki + 64];
    float klo = xr * fr - xi * fi;
    float khi = xr * fi + xi * fr;
    size_t ko = ((size_t)bs * HH + h) * DD + d2;
    out_k[ko]      = klo;
    out_k[ko + 64] = khi;
    size_t kro = (((size_t)(b * HH + h) * SS) + s) * DD + d2;
    kr[kro]      = tf32_rna(klo);
    kr[kro + 64] = tf32_rna(khi);

    size_t vi = base + (size_t)2 * HH * DD + (size_t)h * DD + d2;
    out_v[ko]      = qkv[vi];
    out_v[ko + 64] = qkv[vi + 64];
}

// ---------------- V transpose: out_v [B,S,H,D] -> g_vr tf32 [B,H,D,S] -------
__global__ void transpose_v(const float* __restrict__ out_v,
                            uint32_t* __restrict__ vr) {
    __shared__ float t[32][33];
    const int bh = blockIdx.z, b = bh >> 4, h = bh & 15;
    const int s0 = blockIdx.x * 32, d0 = blockIdx.y * 32;
    for (int i = threadIdx.y; i < 32; i += 8)
        t[i][threadIdx.x] =
            out_v[(((size_t)b * SS + s0 + i) * HH + h) * DD + d0 + threadIdx.x];
    __syncthreads();
    for (int i = threadIdx.y; i < 32; i += 8)
        vr[((size_t)bh * DD + d0 + i) * SS + s0 + threadIdx.x] =
            tf32_rna(t[threadIdx.x][i]);
}

// ============================================================================
// Flash attention on tf32 mma.sync + ldmatrix. BM=128 (8 warps x 16), BN=64.
// K from g_kr (tf32 head-major), V from g_vr (tf32 transposed) — pure float4
// smem fills, no cvt, no transpose conflicts. Causal block skip.
// ============================================================================
#define QP 132
#define KP 132
#define VP 68
#define PP 68
#define FA_WORDS (128*QP + 64*KP + 128*VP + 128*PP)
#define FA_BYTES (FA_WORDS * 4)

__global__ __launch_bounds__(256, 1)
void flash_attn(const float* __restrict__ qkv,
                const uint32_t* __restrict__ kr,
                const uint32_t* __restrict__ vr,
                const float* __restrict__ mask,
                float* __restrict__ attn_out) {
    extern __shared__ uint32_t smw[];
    uint32_t* Qs = smw;                 // [128][QP] tf32
    uint32_t* Ks = Qs + 128 * QP;       // [64][KP]
    uint32_t* Vt = Ks + 64 * KP;        // [128][VP] (V transposed: [d][j])
    uint32_t* Ps = Vt + 128 * VP;       // [128][PP]

    const int qb = blockIdx.x, h = blockIdx.y, b = blockIdx.z;
    const int tid = threadIdx.x, w = tid >> 5, l = tid & 31;
    const int lr = l >> 2, lc = l & 3;
    const float scale = 0.08838834764831845f;   // 1/sqrt(128)

    const int mat = l >> 3;
    const uint32_t sQ = smem_u32(Qs), sK = smem_u32(Ks);
    const uint32_t sV = smem_u32(Vt), sP = smem_u32(Ps);
    const uint32_t qFrag = sQ + (uint32_t)(((w * 16 + (mat & 1) * 8 + (l & 7)) * QP)
                                           + (mat >> 1) * 4) * 4;
    const uint32_t kFrag = sK + (uint32_t)((((mat >> 1) * 8 + (l & 7)) * KP)
                                           + (mat & 1) * 4) * 4;
    const uint32_t vFrag = sV + (uint32_t)((((mat >> 1) * 8 + (l & 7)) * VP)
                                           + (mat & 1) * 4) * 4;
    const uint32_t pFrag = sP + (uint32_t)(((w * 16 + (mat & 1) * 8 + (l & 7)) * PP)
                                           + (mat >> 1) * 4) * 4;

    const uint32_t* krh = kr + ((size_t)(b * HH + h) * SS) * DD;
    const uint32_t* vrh = vr + ((size_t)(b * HH + h) * DD) * SS;

    for (int t = tid; t < 128 * 32; t += 256) {
        int r = t >> 5, c4 = (t & 31) * 4;
        float4 v = *(const float4*)&qkv[((size_t)b * SS + qb * 128 + r) * QKV_W
                                        + h * DD + c4];
        uint32_t* dst = &Qs[r * QP + c4];
        dst[0] = tf32_rna(v.x * scale); dst[1] = tf32_rna(v.y * scale);
        dst[2] = tf32_rna(v.z * scale); dst[3] = tf32_rna(v.w * scale);
    }

    float O[16][4];
#pragma unroll
    for (int nt = 0; nt < 16; nt++)
#pragma unroll
        for (int i = 0; i < 4; i++) O[nt][i] = 0.f;
    float m_lo = -INFINITY, m_hi = -INFINITY, l_lo = 0.f, l_hi = 0.f;

    const int aP = (w * 16 + lr) * PP;
    const int nKV = 2 * qb + 2;

    for (int kb = 0; kb < nKV; kb++) {
        __syncthreads();
        // K: [64][128] head-major rows; V: [128][64] from transposed buffer
        for (int t = tid; t < 64 * 32; t += 256) {
            int r = t >> 5, c4 = (t & 31) * 4;
            *(uint4*)&Ks[r * KP + c4] =
                *(const uint4*)&krh[(size_t)(kb * 64 + r) * DD + c4];
        }
        for (int t = tid; t < 128 * 16; t += 256) {
            int d = t >> 4, j4 = (t & 15) * 4;
            *(uint4*)&Vt[d * VP + j4] =
                *(const uint4*)&vrh[(size_t)d * SS + kb * 64 + j4];
        }
        __syncthreads();

        float S[8][4];
#pragma unroll
        for (int nt = 0; nt < 8; nt++)
#pragma unroll
            for (int i = 0; i < 4; i++) S[nt][i] = 0.f;
#pragma unroll
        for (int ks = 0; ks < 16; ks++) {
            uint32_t af[4];
            ldsm_x4(af, qFrag + ks * 32);
#pragma unroll
            for (int p = 0; p < 4; p++) {
                uint32_t r[4];
                ldsm_x4(r, kFrag + ks * 32 + p * (16 * KP * 4));
                mma_tf32_16x8x8(S[2 * p], af, r);
                mma_tf32_16x8x8(S[2 * p + 1], af, r + 2);
            }
        }

        if (kb >= 2 * qb) {
            const int m_glo = qb * 128 + w * 16 + lr;
            const float* mr0 = &mask[((size_t)b * SS + m_glo) * SS + kb * 64];
            const float* mr1 = mr0 + 8 * SS;
#pragma unroll
            for (int nt = 0; nt < 8; nt++) {
                float2 q0 = *(const float2*)&mr0[nt * 8 + lc * 2];
                float2 q1 = *(const float2*)&mr1[nt * 8 + lc * 2];
                S[nt][0] += q0.x; S[nt][1] += q0.y;
                S[nt][2] += q1.x; S[nt][3] += q1.y;
            }
        }

        float bm_lo = -INFINITY, bm_hi = -INFINITY;
#pragma unroll
        for (int nt = 0; nt < 8; nt++) {
            bm_lo = fmaxf(bm_lo, fmaxf(S[nt][0], S[nt][1]));
            bm_hi = fmaxf(bm_hi, fmaxf(S[nt][2], S[nt][3]));
        }
        bm_lo = fmaxf(bm_lo, __shfl_xor_sync(0xffffffff, bm_lo, 1));
        bm_lo = fmaxf(bm_lo, __shfl_xor_sync(0xffffffff, bm_lo, 2));
        bm_hi = fmaxf(bm_hi, __shfl_xor_sync(0xffffffff, bm_hi, 1));
        bm_hi = fmaxf(bm_hi, __shfl_xor_sync(0xffffffff, bm_hi, 2));
        float mn_lo = fmaxf(m_lo, bm_lo);
        float mn_hi = fmaxf(m_hi, bm_hi);

        float rs_lo = 0.f, rs_hi = 0.f;
#pragma unroll
        for (int nt = 0; nt < 8; nt++) {
            S[nt][0] = __expf(S[nt][0] - mn_lo);
            S[nt][1] = __expf(S[nt][1] - mn_lo);
            S[nt][2] = __expf(S[nt][2] - mn_hi);
            S[nt][3] = __expf(S[nt][3] - mn_hi);
            rs_lo += S[nt][0] + S[nt][1];
            rs_hi += S[nt][2] + S[nt][3];
        }
        rs_lo += __shfl_xor_sync(0xffffffff, rs_lo, 1);
        rs_lo += __shfl_xor_sync(0xffffffff, rs_lo, 2);
        rs_hi += __shfl_xor_sync(0xffffffff, rs_hi, 1);
        rs_hi += __shfl_xor_sync(0xffffffff, rs_hi, 2);

        float al_lo = __expf(m_lo - mn_lo);
        float al_hi = __expf(m_hi - mn_hi);
        l_lo = l_lo * al_lo + rs_lo;
        l_hi = l_hi * al_hi + rs_hi;
        m_lo = mn_lo; m_hi = mn_hi;
#pragma unroll
        for (int nt = 0; nt < 16; nt++) {
            O[nt][0] *= al_lo; O[nt][1] *= al_lo;
            O[nt][2] *= al_hi; O[nt][3] *= al_hi;
        }

#pragma unroll
        for (int nt = 0; nt < 8; nt++) {
            int cw = nt * 8 + lc * 2;
            uint2 p0 = { tf32_rna(S[nt][0]), tf32_rna(S[nt][1]) };
            uint2 p1 = { tf32_rna(S[nt][2]), tf32_rna(S[nt][3]) };
            *(uint2*)&Ps[aP + cw] = p0;
            *(uint2*)&Ps[aP + 8 * PP + cw] = p1;
        }
        __syncwarp();

#pragma unroll
        for (int ks = 0; ks < 8; ks++) {
            uint32_t af[4];
            ldsm_x4(af, pFrag + ks * 32);
#pragma unroll
            for (int p = 0; p < 8; p++) {
                uint32_t r[4];
                ldsm_x4(r, vFrag + ks * 32 + p * (16 * VP * 4));
                mma_tf32_16x8x8(O[2 * p], af, r);
                mma_tf32_16x8x8(O[2 * p + 1], af, r + 2);
            }
        }
        __syncwarp();
    }

    // epilogue: normalize, round to tf32 (GEMM2 input), write [B,S,H,D]
    const float inv_lo = 1.0f / l_lo, inv_hi = 1.0f / l_hi;
    const int m0 = qb * 128 + w * 16 + lr;
#pragma unroll
    for (int nt = 0; nt < 16; nt++) {
        int d = nt * 8 + lc * 2;
        uint2 v0 = { tf32_rna(O[nt][0] * inv_lo), tf32_rna(O[nt][1] * inv_lo) };
        uint2 v1 = { tf32_rna(O[nt][2] * inv_hi), tf32_rna(O[nt][3] * inv_hi) };
        *(uint2*)&attn_out[(((size_t)b * SS + m0) * HH + h) * DD + d] = v0;
        *(uint2*)&attn_out[(((size_t)b * SS + m0 + 8) * HH + h) * DD + d] = v1;
    }
}

// ---------------- launch ----------------------------------------------------
extern "C" void kernel_launch(void* const* d_in, const int* in_sizes, int n_in,
                              void* d_out, int out_size) {
    const float* x      = (const float*)d_in[0];
    const float* f_r    = (const float*)d_in[1];
    const float* f_i    = (const float*)d_in[2];
    const float* mask   = (const float*)d_in[3];
    const float* W_qkv  = (const float*)d_in[4];
    const float* b_qkv  = (const float*)d_in[5];
    const float* W_o    = (const float*)d_in[6];

    float* out   = (float*)d_out;
    float* out_k = out   + (size_t)BB * SS * NSTATE;
    float* out_v = out_k + (size_t)BB * SS * HH * DD;

    float* qkv = nullptr;  cudaGetSymbolAddress((void**)&qkv,  g_qkv);
    float* attn = nullptr; cudaGetSymbolAddress((void**)&attn, g_attn);
    float* xr = nullptr;   cudaGetSymbolAddress((void**)&xr,   g_xr);
    float* wq = nullptr;   cudaGetSymbolAddress((void**)&wq,   g_wq);
    float* wo = nullptr;   cudaGetSymbolAddress((void**)&wo,   g_wo);
    uint32_t* kr = nullptr; cudaGetSymbolAddress((void**)&kr,  g_kr);
    uint32_t* vr = nullptr; cudaGetSymbolAddress((void**)&vr,  g_vr);

    const int M = BB * SS;   // 4096

    cudaFuncSetAttribute(gemm_mma, cudaFuncAttributeMaxDynamicSharedMemorySize,
                         G_SMEM);
    cudaFuncSetAttribute(flash_attn, cudaFuncAttributeMaxDynamicSharedMemorySize,
                         FA_BYTES);

    // 0) pre-round GEMM inputs to tf32
    {
        int n4x = (M * NSTATE) / 4;
        round_tf32<<<(n4x + 255) / 256, 256>>>(x, xr, n4x);
        int n4q = (QKV_W * NSTATE) / 4;
        round_tf32<<<(n4q + 255) / 256, 256>>>(W_qkv, wq, n4q);
        int n4o = (NSTATE * NSTATE) / 4;
        round_tf32<<<(n4o + 255) / 256, 256>>>(W_o, wo, n4o);
    }

    // 1) QKV projection (tf32 mma.sync, cp.async 4-stage)
    gemm_mma<<<dim3(QKV_W / 128, M / 128), 256, G_SMEM>>>(
        xr, wq, b_qkv, qkv, M, QKV_W, NSTATE);
    // 2) RoPE q,k; scatter k,v to output; k tf32 head-major
    rope_scatter<<<(BB * SS * HH * 64) / 256, 256>>>(qkv, f_r, f_i,
                                                     out_k, out_v, kr);
    // 2b) V transpose to [B,H,D,S] tf32
    transpose_v<<<dim3(SS / 32, DD / 32, BB * HH), dim3(32, 8)>>>(out_v, vr);
    // 3) attention (tf32 mma + ldmatrix, causal block skip)
    flash_attn<<<dim3(SS / 128, HH, BB), 256, FA_BYTES>>>(qkv, kr, vr,
                                                          mask, attn);
    // 4) output projection (tf32 mma.sync, cp.async 4-stage)
    gemm_mma<<<dim3(NSTATE / 128, M / 128), 256, G_SMEM>>>(
        attn, wo, nullptr, out, M, NSTATE, NSTATE);
}

// round 9
// speedup vs baseline: 1.7014x; 1.4796x over previous
#include <cuda_runtime.h>
#include <cuda_fp16.h>
#include <cstdint>
#include <math.h>

// Problem constants
#define BB 2
#define SS 2048
#define HH 16
#define DD 128
#define NSTATE 2048
#define QKV_W (3*HH*DD)   // 6144

// ---------------- scratch (device globals; no runtime alloc) ----------------
__device__ float  g_qkv[(size_t)BB * SS * QKV_W];     // [B,S,6144] fp32
__device__ __half g_attnh[(size_t)BB * SS * HH * DD]; // attn out, half
__device__ __half g_xh[(size_t)BB * SS * NSTATE];     // x half
__device__ __half g_wqh[(size_t)QKV_W * NSTATE];      // W_qkv half
__device__ __half g_woh[(size_t)NSTATE * NSTATE];     // W_o half
__device__ __half g_kh[(size_t)BB * HH * SS * DD];    // k half, [B,H,S,D]
__device__ __half g_vh[(size_t)BB * HH * DD * SS];    // v half, [B,H,D,S]

// ---------------- helpers ----------------------------------------------------
__device__ __forceinline__ uint32_t smem_u32(const void* p) {
    uint32_t a;
    asm("{ .reg .u64 t; cvta.to.shared.u64 t, %1; cvt.u32.u64 %0, t; }"
        : "=r"(a) : "l"(p));
    return a;
}
__device__ __forceinline__ void mma_f16(float* c, const uint32_t* a,
                                        const uint32_t* b) {
    asm volatile(
        "mma.sync.aligned.m16n8k16.row.col.f32.f16.f16.f32 "
        "{%0,%1,%2,%3}, {%4,%5,%6,%7}, {%8,%9}, {%0,%1,%2,%3};\n"
        : "+f"(c[0]), "+f"(c[1]), "+f"(c[2]), "+f"(c[3])
        : "r"(a[0]), "r"(a[1]), "r"(a[2]), "r"(a[3]), "r"(b[0]), "r"(b[1]));
}
__device__ __forceinline__ void ldsm_x4(uint32_t* r, uint32_t addr) {
    asm volatile("ldmatrix.sync.aligned.m8n8.x4.shared.b16 {%0,%1,%2,%3}, [%4];"
                 : "=r"(r[0]), "=r"(r[1]), "=r"(r[2]), "=r"(r[3]) : "r"(addr));
}
__device__ __forceinline__ void cp16(uint32_t s, const void* g) {
    asm volatile("cp.async.cg.shared.global [%0], [%1], 16;"
                 :: "r"(s), "l"(g) : "memory");
}
#define CP_COMMIT() asm volatile("cp.async.commit_group;" ::: "memory")
#define CP_WAIT2()  asm volatile("cp.async.wait_group 2;"  ::: "memory")

// ---------------- fp32 -> fp16 pre-round pass --------------------------------
__global__ void round_half(const float* __restrict__ src,
                           __half* __restrict__ dst, int n4) {
    int i = blockIdx.x * blockDim.x + threadIdx.x;
    if (i >= n4) return;
    float4 v = ((const float4*)src)[i];
    __half2 h0 = __floats2half2_rn(v.x, v.y);
    __half2 h1 = __floats2half2_rn(v.z, v.w);
    uint2 o = { *(uint32_t*)&h0, *(uint32_t*)&h1 };
    ((uint2*)dst)[i] = o;
}

// ============================================================================
// fp16 mma.sync GEMM (NT): C[m,n] = sum_k A[m,k]*B[n,k] (+bias[n]), fp32 acc
// Block 128x128, BK=32 halves, 8 warps (4x2), warp tile 32x64,
// 4-stage cp.async ring (single barrier / iter), TPH=40-half rows, ldmatrix.
// ============================================================================
#define TPH 40                                // halves; 80B row (5x16B, odd)
#define G_NSTG 4
#define G_AB (128 * TPH * 2)                  // 10240 B per operand tile
#define G_STG (2 * G_AB)                      // 20480 B per stage
#define G_SMEM (G_NSTG * G_STG)               // 81920 B

__device__ __forceinline__ void gemm_issue(uint32_t sbase,
                                           const __half* __restrict__ A,
                                           const __half* __restrict__ B,
                                           int m0, int n0, int K, int k0,
                                           int tid) {
    const int row = tid >> 2, seg = tid & 3;     // 64 rows x 4 segs per pass
    cp16(sbase + (uint32_t)(row * TPH + seg * 8) * 2,
         &A[(size_t)(m0 + row) * K + k0 + seg * 8]);
    cp16(sbase + (uint32_t)((row + 64) * TPH + seg * 8) * 2,
         &A[(size_t)(m0 + row + 64) * K + k0 + seg * 8]);
    const uint32_t sB = sbase + G_AB;
    cp16(sB + (uint32_t)(row * TPH + seg * 8) * 2,
         &B[(size_t)(n0 + row) * K + k0 + seg * 8]);
    cp16(sB + (uint32_t)((row + 64) * TPH + seg * 8) * 2,
         &B[(size_t)(n0 + row + 64) * K + k0 + seg * 8]);
}

__global__ __launch_bounds__(256, 2)
void gemm_mma(const __half* __restrict__ A, const __half* __restrict__ B,
              const float* __restrict__ bias, float* __restrict__ C,
              int M, int N, int K) {
    extern __shared__ uint32_t dynsm[];
    const uint32_t sb = smem_u32(dynsm);

    const int tid = threadIdx.x;
    const int w = tid >> 5, l = tid & 31;
    const int lr = l >> 2, lc = l & 3;
    const int wm = w >> 1, wn = w & 1;           // 4 (m) x 2 (n)
    const int m0 = blockIdx.y * 128, n0 = blockIdx.x * 128;
    const int mat = l >> 3;

    // A frag: row=(mat&1)*8+(l&7) within 16-row tile, k-off=(mat>>1)*8 halves
    const uint32_t aOff = (uint32_t)(((wm * 32 + (mat & 1) * 8 + (l & 7)) * TPH)
                                     + (mat >> 1) * 8) * 2;
    // B frag: n-row=(mat>>1)*8+(l&7) within 16-n group, k-off=(mat&1)*8
    const uint32_t bOff = G_AB
                        + (uint32_t)(((wn * 64 + (mat >> 1) * 8 + (l & 7)) * TPH)
                                     + (mat & 1) * 8) * 2;

    float acc[2][8][4];
#pragma unroll
    for (int mt = 0; mt < 2; mt++)
#pragma unroll
        for (int nt = 0; nt < 8; nt++)
#pragma unroll
            for (int i = 0; i < 4; i++) acc[mt][nt][i] = 0.f;

    const int NC = K / 32;

#pragma unroll
    for (int s = 0; s < G_NSTG - 1; s++) {
        gemm_issue(sb + s * G_STG, A, B, m0, n0, K, s * 32, tid);
        CP_COMMIT();
    }

    for (int c = 0; c < NC; c++) {
        CP_WAIT2();
        __syncthreads();

        const int nc = c + G_NSTG - 1;
        if (nc < NC)
            gemm_issue(sb + (nc % G_NSTG) * G_STG, A, B, m0, n0, K, nc * 32, tid);
        CP_COMMIT();

        const uint32_t st = sb + (c % G_NSTG) * G_STG;
#pragma unroll
        for (int kk = 0; kk < 2; kk++) {        // two k16 sub-steps of BK=32
            uint32_t af[2][4];
            ldsm_x4(af[0], st + aOff + kk * 32);
            ldsm_x4(af[1], st + aOff + kk * 32 + 16 * TPH * 2);
#pragma unroll
            for (int p = 0; p < 4; p++) {
                uint32_t r[4];
                ldsm_x4(r, st + bOff + kk * 32 + p * (16 * TPH * 2));
#pragma unroll
                for (int mt = 0; mt < 2; mt++) {
                    mma_f16(acc[mt][2 * p], af[mt], r);       // {r0,r1}
                    mma_f16(acc[mt][2 * p + 1], af[mt], r + 2); // {r2,r3}
                }
            }
        }
        // no trailing barrier: next iteration's barrier protects stage reuse
    }

#pragma unroll
    for (int mt = 0; mt < 2; mt++) {
        int m = m0 + wm * 32 + mt * 16 + lr;
#pragma unroll
        for (int nt = 0; nt < 8; nt++) {
            int n = n0 + wn * 64 + nt * 8 + lc * 2;
            float bx = 0.f, by = 0.f;
            if (bias) { bx = bias[n]; by = bias[n + 1]; }
            float2 v0 = { acc[mt][nt][0] + bx, acc[mt][nt][1] + by };
            float2 v1 = { acc[mt][nt][2] + bx, acc[mt][nt][3] + by };
            *(float2*)&C[(size_t)m * N + n] = v0;
            *(float2*)&C[(size_t)(m + 8) * N + n] = v1;
        }
    }
}

// ---------------- RoPE: q in place; k -> out_k (fp32) + g_kh (half, head-major)
__global__ void rope_scatter(float* __restrict__ qkv,
                             const float* __restrict__ f_r,
                             const float* __restrict__ f_i,
                             float* __restrict__ out_k,
                             float* __restrict__ out_v,
                             __half* __restrict__ kh) {
    int idx = blockIdx.x * blockDim.x + threadIdx.x;
    if (idx >= BB * SS * HH * 64) return;
    int d2 = idx & 63;
    int h  = (idx >> 6) & (HH - 1);
    int bs = idx >> 10;
    int b = bs >> 11, s = bs & (SS - 1);

    float fr = f_r[(size_t)bs * 64 + d2];
    float fi = f_i[(size_t)bs * 64 + d2];

    size_t base = (size_t)bs * QKV_W;
    size_t qi = base + (size_t)h * DD + d2;
    float xr = qkv[qi], xi = qkv[qi + 64];
    qkv[qi]      = xr * fr - xi * fi;
    qkv[qi + 64] = xr * fi + xi * fr;

    size_t ki = base + (size_t)HH * DD + (size_t)h * DD + d2;
    xr = qkv[ki]; xi = qkv[ki + 64];
    float klo = xr * fr - xi * fi;
    float khi = xr * fi + xi * fr;
    size_t ko = ((size_t)bs * HH + h) * DD + d2;
    out_k[ko]      = klo;
    out_k[ko + 64] = khi;
    size_t kro = (((size_t)(b * HH + h) * SS) + s) * DD + d2;
    kh[kro]      = __float2half_rn(klo);
    kh[kro + 64] = __float2half_rn(khi);

    size_t vi = base + (size_t)2 * HH * DD + (size_t)h * DD + d2;
    out_v[ko]      = qkv[vi];
    out_v[ko + 64] = qkv[vi + 64];
}

// ---------------- V transpose: out_v [B,S,H,D] -> g_vh half [B,H,D,S] -------
__global__ void transpose_v(const float* __restrict__ out_v,
                            __half* __restrict__ vh) {
    __shared__ float t[32][33];
    const int bh = blockIdx.z, b = bh >> 4, h = bh & 15;
    const int s0 = blockIdx.x * 32, d0 = blockIdx.y * 32;
    for (int i = threadIdx.y; i < 32; i += 8)
        t[i][threadIdx.x] =
            out_v[(((size_t)b * SS + s0 + i) * HH + h) * DD + d0 + threadIdx.x];
    __syncthreads();
    for (int i = threadIdx.y; i < 32; i += 8)
        vh[((size_t)bh * DD + d0 + i) * SS + s0 + threadIdx.x] =
            __float2half_rn(t[threadIdx.x][i]);
}

// ============================================================================
// Flash attention, fp16 mma.sync + ldmatrix. BM=128 (8 warps x 16), BN=64.
// Qs[128][136h] Ks[64][136h] Vt[128][72h] Ps[128][72h]. Causal block skip.
// Writes half attn (GEMM2 input).
// ============================================================================
#define QSTR 136   // halves; 272B row (17x16B, odd)
#define VSTR 72    // halves; 144B row (9x16B, odd)
#define FA_BYTES ((128*QSTR + 64*QSTR + 128*VSTR + 128*VSTR) * 2)

__global__ __launch_bounds__(256, 1)
void flash_attn(const float* __restrict__ qkv,
                const __half* __restrict__ kh,
                const __half* __restrict__ vh,
                const float* __restrict__ mask,
                __half* __restrict__ attn_out) {
    extern __shared__ __half smh[];
    __half* Qs = smh;                  // [128][QSTR]
    __half* Ks = Qs + 128 * QSTR;      // [64][QSTR]
    __half* Vt = Ks + 64 * QSTR;       // [128][VSTR]  (V transposed: [d][j])
    __half* Ps = Vt + 128 * VSTR;      // [128][VSTR]

    const int qb = blockIdx.x, h = blockIdx.y, b = blockIdx.z;
    const int tid = threadIdx.x, w = tid >> 5, l = tid & 31;
    const int lr = l >> 2, lc = l & 3;
    const float scale = 0.08838834764831845f;   // 1/sqrt(128)

    const int mat = l >> 3;
    const uint32_t sQ = smem_u32(Qs), sK = smem_u32(Ks);
    const uint32_t sV = smem_u32(Vt), sP = smem_u32(Ps);
    const uint32_t qFrag = sQ + (uint32_t)(((w * 16 + (mat & 1) * 8 + (l & 7)) * QSTR)
                                           + (mat >> 1) * 8) * 2;
    const uint32_t kFrag = sK + (uint32_t)((((mat >> 1) * 8 + (l & 7)) * QSTR)
                                           + (mat & 1) * 8) * 2;
    const uint32_t vFrag = sV + (uint32_t)((((mat >> 1) * 8 + (l & 7)) * VSTR)
                                           + (mat & 1) * 8) * 2;
    const uint32_t pFrag = sP + (uint32_t)(((w * 16 + (mat & 1) * 8 + (l & 7)) * VSTR)
                                           + (mat >> 1) * 8) * 2;

    const __half* krh = kh + ((size_t)(b * HH + h) * SS) * DD;
    const __half* vrh = vh + ((size_t)(b * HH + h) * DD) * SS;

    // ---- load Q tile (prescaled, half) ----
    for (int t = tid; t < 128 * 32; t += 256) {
        int r = t >> 5, c4 = (t & 31) * 4;
        float4 v = *(const float4*)&qkv[((size_t)b * SS + qb * 128 + r) * QKV_W
                                        + h * DD + c4];
        __half2 h0 = __floats2half2_rn(v.x * scale, v.y * scale);
        __half2 h1 = __floats2half2_rn(v.z * scale, v.w * scale);
        uint2 o = { *(uint32_t*)&h0, *(uint32_t*)&h1 };
        *(uint2*)&Qs[r * QSTR + c4] = o;
    }

    float O[16][4];
#pragma unroll
    for (int nt = 0; nt < 16; nt++)
#pragma unroll
        for (int i = 0; i < 4; i++) O[nt][i] = 0.f;
    float m_lo = -INFINITY, m_hi = -INFINITY, l_lo = 0.f, l_hi = 0.f;

    const int nKV = 2 * qb + 2;

    for (int kb = 0; kb < nKV; kb++) {
        __syncthreads();
        // K: [64][128] halves; V: [128][64] halves (transposed buffer)
        for (int t = tid; t < 64 * 16; t += 256) {
            int r = t >> 4, c8 = t & 15;
            *(uint4*)&Ks[r * QSTR + c8 * 8] =
                *(const uint4*)&krh[(size_t)(kb * 64 + r) * DD + c8 * 8];
        }
        for (int t = tid; t < 128 * 8; t += 256) {
            int d = t >> 3, j8 = t & 7;
            *(uint4*)&Vt[d * VSTR + j8 * 8] =
                *(const uint4*)&vrh[(size_t)d * SS + kb * 64 + j8 * 8];
        }
        __syncthreads();

        // ---- S = Q K^T : m16 x n64 x k128 per warp (8 k16 steps) ----
        float S[8][4];
#pragma unroll
        for (int nt = 0; nt < 8; nt++)
#pragma unroll
            for (int i = 0; i < 4; i++) S[nt][i] = 0.f;
#pragma unroll
        for (int ks = 0; ks < 8; ks++) {
            uint32_t af[4];
            ldsm_x4(af, qFrag + ks * 32);
#pragma unroll
            for (int p = 0; p < 4; p++) {
                uint32_t r[4];
                ldsm_x4(r, kFrag + ks * 32 + p * (16 * QSTR * 2));
                mma_f16(S[2 * p], af, r);
                mma_f16(S[2 * p + 1], af, r + 2);
            }
        }

        if (kb >= 2 * qb) {
            const int m_glo = qb * 128 + w * 16 + lr;
            const float* mr0 = &mask[((size_t)b * SS + m_glo) * SS + kb * 64];
            const float* mr1 = mr0 + 8 * SS;
#pragma unroll
            for (int nt = 0; nt < 8; nt++) {
                float2 q0 = *(const float2*)&mr0[nt * 8 + lc * 2];
                float2 q1 = *(const float2*)&mr1[nt * 8 + lc * 2];
                S[nt][0] += q0.x; S[nt][1] += q0.y;
                S[nt][2] += q1.x; S[nt][3] += q1.y;
            }
        }

        float bm_lo = -INFINITY, bm_hi = -INFINITY;
#pragma unroll
        for (int nt = 0; nt < 8; nt++) {
            bm_lo = fmaxf(bm_lo, fmaxf(S[nt][0], S[nt][1]));
            bm_hi = fmaxf(bm_hi, fmaxf(S[nt][2], S[nt][3]));
        }
        bm_lo = fmaxf(bm_lo, __shfl_xor_sync(0xffffffff, bm_lo, 1));
        bm_lo = fmaxf(bm_lo, __shfl_xor_sync(0xffffffff, bm_lo, 2));
        bm_hi = fmaxf(bm_hi, __shfl_xor_sync(0xffffffff, bm_hi, 1));
        bm_hi = fmaxf(bm_hi, __shfl_xor_sync(0xffffffff, bm_hi, 2));
        float mn_lo = fmaxf(m_lo, bm_lo);
        float mn_hi = fmaxf(m_hi, bm_hi);

        float rs_lo = 0.f, rs_hi = 0.f;
#pragma unroll
        for (int nt = 0; nt < 8; nt++) {
            S[nt][0] = __expf(S[nt][0] - mn_lo);
            S[nt][1] = __expf(S[nt][1] - mn_lo);
            S[nt][2] = __expf(S[nt][2] - mn_hi);
            S[nt][3] = __expf(S[nt][3] - mn_hi);
            rs_lo += S[nt][0] + S[nt][1];
            rs_hi += S[nt][2] + S[nt][3];
        }
        rs_lo += __shfl_xor_sync(0xffffffff, rs_lo, 1);
        rs_lo += __shfl_xor_sync(0xffffffff, rs_lo, 2);
        rs_hi += __shfl_xor_sync(0xffffffff, rs_hi, 1);
        rs_hi += __shfl_xor_sync(0xffffffff, rs_hi, 2);

        float al_lo = __expf(m_lo - mn_lo);
        float al_hi = __expf(m_hi - mn_hi);
        l_lo = l_lo * al_lo + rs_lo;
        l_hi = l_hi * al_hi + rs_hi;
        m_lo = mn_lo; m_hi = mn_hi;
#pragma unroll
        for (int nt = 0; nt < 16; nt++) {
            O[nt][0] *= al_lo; O[nt][1] *= al_lo;
            O[nt][2] *= al_hi; O[nt][3] *= al_hi;
        }

        // ---- stage P (warp-local) as half ----
#pragma unroll
        for (int nt = 0; nt < 8; nt++) {
            int cw = nt * 8 + lc * 2;
            __half2 p0 = __floats2half2_rn(S[nt][0], S[nt][1]);
            __half2 p1 = __floats2half2_rn(S[nt][2], S[nt][3]);
            *(__half2*)&Ps[(w * 16 + lr) * VSTR + cw] = p0;
            *(__half2*)&Ps[(w * 16 + lr + 8) * VSTR + cw] = p1;
        }
        __syncwarp();

        // ---- O += P V : m16 x n128 x k64 per warp (4 k16 steps) ----
#pragma unroll
        for (int ks = 0; ks < 4; ks++) {
            uint32_t af[4];
            ldsm_x4(af, pFrag + ks * 32);
#pragma unroll
            for (int p = 0; p < 8; p++) {
                uint32_t r[4];
                ldsm_x4(r, vFrag + ks * 32 + p * (16 * VSTR * 2));
                mma_f16(O[2 * p], af, r);
                mma_f16(O[2 * p + 1], af, r + 2);
            }
        }
        __syncwarp();
    }

    // epilogue: normalize, write half attn [B,S,H,D]
    const float inv_lo = 1.0f / l_lo, inv_hi = 1.0f / l_hi;
    const int m0 = qb * 128 + w * 16 + lr;
#pragma unroll
    for (int nt = 0; nt < 16; nt++) {
        int d = nt * 8 + lc * 2;
        __half2 v0 = __floats2half2_rn(O[nt][0] * inv_lo, O[nt][1] * inv_lo);
        __half2 v1 = __floats2half2_rn(O[nt][2] * inv_hi, O[nt][3] * inv_hi);
        *(__half2*)&attn_out[(((size_t)b * SS + m0) * HH + h) * DD + d] = v0;
        *(__half2*)&attn_out[(((size_t)b * SS + m0 + 8) * HH + h) * DD + d] = v1;
    }
}

// ---------------- launch ----------------------------------------------------
extern "C" void kernel_launch(void* const* d_in, const int* in_sizes, int n_in,
                              void* d_out, int out_size) {
    const float* x      = (const float*)d_in[0];
    const float* f_r    = (const float*)d_in[1];
    const float* f_i    = (const float*)d_in[2];
    const float* mask   = (const float*)d_in[3];
    const float* W_qkv  = (const float*)d_in[4];
    const float* b_qkv  = (const float*)d_in[5];
    const float* W_o    = (const float*)d_in[6];

    float* out   = (float*)d_out;
    float* out_k = out   + (size_t)BB * SS * NSTATE;
    float* out_v = out_k + (size_t)BB * SS * HH * DD;

    float* qkv = nullptr;    cudaGetSymbolAddress((void**)&qkv,   g_qkv);
    __half* attnh = nullptr; cudaGetSymbolAddress((void**)&attnh, g_attnh);
    __half* xh = nullptr;    cudaGetSymbolAddress((void**)&xh,    g_xh);
    __half* wqh = nullptr;   cudaGetSymbolAddress((void**)&wqh,   g_wqh);
    __half* woh = nullptr;   cudaGetSymbolAddress((void**)&woh,   g_woh);
    __half* kh = nullptr;    cudaGetSymbolAddress((void**)&kh,    g_kh);
    __half* vh = nullptr;    cudaGetSymbolAddress((void**)&vh,    g_vh);

    const int M = BB * SS;   // 4096

    cudaFuncSetAttribute(gemm_mma, cudaFuncAttributeMaxDynamicSharedMemorySize,
                         G_SMEM);
    cudaFuncSetAttribute(flash_attn, cudaFuncAttributeMaxDynamicSharedMemorySize,
                         FA_BYTES);

    // 0) pre-round GEMM inputs to fp16
    {
        int n4x = (M * NSTATE) / 4;
        round_half<<<(n4x + 255) / 256, 256>>>(x, xh, n4x);
        int n4q = (QKV_W * NSTATE) / 4;
        round_half<<<(n4q + 255) / 256, 256>>>(W_qkv, wqh, n4q);
        int n4o = (NSTATE * NSTATE) / 4;
        round_half<<<(n4o + 255) / 256, 256>>>(W_o, woh, n4o);
    }

    // 1) QKV projection (fp16 mma.sync, cp.async 4-stage)
    gemm_mma<<<dim3(QKV_W / 128, M / 128), 256, G_SMEM>>>(
        xh, wqh, b_qkv, qkv, M, QKV_W, NSTATE);
    // 2) RoPE q,k; scatter k,v to output; k half head-major
    rope_scatter<<<(BB * SS * HH * 64) / 256, 256>>>(qkv, f_r, f_i,
                                                     out_k, out_v, kh);
    // 2b) V transpose to [B,H,D,S] half
    transpose_v<<<dim3(SS / 32, DD / 32, BB * HH), dim3(32, 8)>>>(out_v, vh);
    // 3) attention (fp16 mma + ldmatrix, causal block skip)
    flash_attn<<<dim3(SS / 128, HH, BB), 256, FA_BYTES>>>(qkv, kh, vh,
                                                          mask, attnh);
    // 4) output projection (fp16 mma.sync, cp.async 4-stage)
    gemm_mma<<<dim3(NSTATE / 128, M / 128), 256, G_SMEM>>>(
        attnh, woh, nullptr, out, M, NSTATE, NSTATE);
}

// round 10
// speedup vs baseline: 2.2395x; 1.3162x over previous
#include <cuda_runtime.h>
#include <cuda_fp16.h>
#include <cstdint>
#include <math.h>

// Problem constants
#define BB 2
#define SS 2048
#define HH 16
#define DD 128
#define NSTATE 2048
#define QKV_W (3*HH*DD)   // 6144

// ---------------- scratch (device globals; no runtime alloc) ----------------
__device__ float  g_qkv[(size_t)BB * SS * QKV_W];     // [B,S,6144] fp32
__device__ __half g_attnh[(size_t)BB * SS * HH * DD]; // attn out, half
__device__ __half g_xh[(size_t)BB * SS * NSTATE];     // x half
__device__ __half g_wqh[(size_t)QKV_W * NSTATE];      // W_qkv half
__device__ __half g_woh[(size_t)NSTATE * NSTATE];     // W_o half
__device__ __half g_kh[(size_t)BB * HH * SS * DD];    // k half, [B,H,S,D]
__device__ __half g_vh[(size_t)BB * HH * DD * SS];    // v half, [B,H,D,S]

// ---------------- helpers ----------------------------------------------------
__device__ __forceinline__ uint32_t smem_u32(const void* p) {
    uint32_t a;
    asm("{ .reg .u64 t; cvta.to.shared.u64 t, %1; cvt.u32.u64 %0, t; }"
        : "=r"(a) : "l"(p));
    return a;
}
__device__ __forceinline__ void mma_f16(float* c, const uint32_t* a,
                                        const uint32_t* b) {
    asm volatile(
        "mma.sync.aligned.m16n8k16.row.col.f32.f16.f16.f32 "
        "{%0,%1,%2,%3}, {%4,%5,%6,%7}, {%8,%9}, {%0,%1,%2,%3};\n"
        : "+f"(c[0]), "+f"(c[1]), "+f"(c[2]), "+f"(c[3])
        : "r"(a[0]), "r"(a[1]), "r"(a[2]), "r"(a[3]), "r"(b[0]), "r"(b[1]));
}
__device__ __forceinline__ void ldsm_x4(uint32_t* r, uint32_t addr) {
    asm volatile("ldmatrix.sync.aligned.m8n8.x4.shared.b16 {%0,%1,%2,%3}, [%4];"
                 : "=r"(r[0]), "=r"(r[1]), "=r"(r[2]), "=r"(r[3]) : "r"(addr));
}
__device__ __forceinline__ void cp16(uint32_t s, const void* g) {
    asm volatile("cp.async.cg.shared.global [%0], [%1], 16;"
                 :: "r"(s), "l"(g) : "memory");
}
#define CP_COMMIT() asm volatile("cp.async.commit_group;" ::: "memory")
#define CP_WAIT2()  asm volatile("cp.async.wait_group 2;"  ::: "memory")
#define CP_WAIT0()  asm volatile("cp.async.wait_group 0;"  ::: "memory")

// ---------------- fp32 -> fp16 pre-round pass --------------------------------
__global__ void round_half(const float* __restrict__ src,
                           __half* __restrict__ dst, int n4) {
    int i = blockIdx.x * blockDim.x + threadIdx.x;
    if (i >= n4) return;
    float4 v = ((const float4*)src)[i];
    __half2 h0 = __floats2half2_rn(v.x, v.y);
    __half2 h1 = __floats2half2_rn(v.z, v.w);
    uint2 o = { *(uint32_t*)&h0, *(uint32_t*)&h1 };
    ((uint2*)dst)[i] = o;
}

// ============================================================================
// fp16 mma.sync GEMM (NT): C[m,n] = sum_k A[m,k]*B[n,k] (+bias[n]), fp32 acc
// Block 128x128, BK=32 halves, 8 warps (4x2), warp tile 32x64,
// 4-stage cp.async ring (single barrier / iter), TPH=40-half rows, ldmatrix.
// ============================================================================
#define TPH 40                                // halves; 80B row (5x16B, odd)
#define G_NSTG 4
#define G_AB (128 * TPH * 2)                  // 10240 B per operand tile
#define G_STG (2 * G_AB)                      // 20480 B per stage
#define G_SMEM (G_NSTG * G_STG)               // 81920 B

__device__ __forceinline__ void gemm_issue(uint32_t sbase,
                                           const __half* __restrict__ A,
                                           const __half* __restrict__ B,
                                           int m0, int n0, int K, int k0,
                                           int tid) {
    const int row = tid >> 2, seg = tid & 3;     // 64 rows x 4 segs per pass
    cp16(sbase + (uint32_t)(row * TPH + seg * 8) * 2,
         &A[(size_t)(m0 + row) * K + k0 + seg * 8]);
    cp16(sbase + (uint32_t)((row + 64) * TPH + seg * 8) * 2,
         &A[(size_t)(m0 + row + 64) * K + k0 + seg * 8]);
    const uint32_t sB = sbase + G_AB;
    cp16(sB + (uint32_t)(row * TPH + seg * 8) * 2,
         &B[(size_t)(n0 + row) * K + k0 + seg * 8]);
    cp16(sB + (uint32_t)((row + 64) * TPH + seg * 8) * 2,
         &B[(size_t)(n0 + row + 64) * K + k0 + seg * 8]);
}

__global__ __launch_bounds__(256, 2)
void gemm_mma(const __half* __restrict__ A, const __half* __restrict__ B,
              const float* __restrict__ bias, float* __restrict__ C,
              int M, int N, int K) {
    extern __shared__ uint32_t dynsm[];
    const uint32_t sb = smem_u32(dynsm);

    const int tid = threadIdx.x;
    const int w = tid >> 5, l = tid & 31;
    const int lr = l >> 2, lc = l & 3;
    const int wm = w >> 1, wn = w & 1;           // 4 (m) x 2 (n)
    const int m0 = blockIdx.y * 128, n0 = blockIdx.x * 128;
    const int mat = l >> 3;

    const uint32_t aOff = (uint32_t)(((wm * 32 + (mat & 1) * 8 + (l & 7)) * TPH)
                                     + (mat >> 1) * 8) * 2;
    const uint32_t bOff = G_AB
                        + (uint32_t)(((wn * 64 + (mat >> 1) * 8 + (l & 7)) * TPH)
                                     + (mat & 1) * 8) * 2;

    float acc[2][8][4];
#pragma unroll
    for (int mt = 0; mt < 2; mt++)
#pragma unroll
        for (int nt = 0; nt < 8; nt++)
#pragma unroll
            for (int i = 0; i < 4; i++) acc[mt][nt][i] = 0.f;

    const int NC = K / 32;

#pragma unroll
    for (int s = 0; s < G_NSTG - 1; s++) {
        gemm_issue(sb + s * G_STG, A, B, m0, n0, K, s * 32, tid);
        CP_COMMIT();
    }

    for (int c = 0; c < NC; c++) {
        CP_WAIT2();
        __syncthreads();

        const int nc = c + G_NSTG - 1;
        if (nc < NC)
            gemm_issue(sb + (nc % G_NSTG) * G_STG, A, B, m0, n0, K, nc * 32, tid);
        CP_COMMIT();

        const uint32_t st = sb + (c % G_NSTG) * G_STG;
#pragma unroll
        for (int kk = 0; kk < 2; kk++) {
            uint32_t af[2][4];
            ldsm_x4(af[0], st + aOff + kk * 32);
            ldsm_x4(af[1], st + aOff + kk * 32 + 16 * TPH * 2);
#pragma unroll
            for (int p = 0; p < 4; p++) {
                uint32_t r[4];
                ldsm_x4(r, st + bOff + kk * 32 + p * (16 * TPH * 2));
#pragma unroll
                for (int mt = 0; mt < 2; mt++) {
                    mma_f16(acc[mt][2 * p], af[mt], r);
                    mma_f16(acc[mt][2 * p + 1], af[mt], r + 2);
                }
            }
        }
    }

#pragma unroll
    for (int mt = 0; mt < 2; mt++) {
        int m = m0 + wm * 32 + mt * 16 + lr;
#pragma unroll
        for (int nt = 0; nt < 8; nt++) {
            int n = n0 + wn * 64 + nt * 8 + lc * 2;
            float bx = 0.f, by = 0.f;
            if (bias) { bx = bias[n]; by = bias[n + 1]; }
            float2 v0 = { acc[mt][nt][0] + bx, acc[mt][nt][1] + by };
            float2 v1 = { acc[mt][nt][2] + bx, acc[mt][nt][3] + by };
            *(float2*)&C[(size_t)m * N + n] = v0;
            *(float2*)&C[(size_t)(m + 8) * N + n] = v1;
        }
    }
}

// ---------------- RoPE: q in place; k -> out_k (fp32) + g_kh (half, head-major)
__global__ void rope_scatter(float* __restrict__ qkv,
                             const float* __restrict__ f_r,
                             const float* __restrict__ f_i,
                             float* __restrict__ out_k,
                             float* __restrict__ out_v,
                             __half* __restrict__ kh) {
    int idx = blockIdx.x * blockDim.x + threadIdx.x;
    if (idx >= BB * SS * HH * 64) return;
    int d2 = idx & 63;
    int h  = (idx >> 6) & (HH - 1);
    int bs = idx >> 10;
    int b = bs >> 11, s = bs & (SS - 1);

    float fr = f_r[(size_t)bs * 64 + d2];
    float fi = f_i[(size_t)bs * 64 + d2];

    size_t base = (size_t)bs * QKV_W;
    size_t qi = base + (size_t)h * DD + d2;
    float xr = qkv[qi], xi = qkv[qi + 64];
    qkv[qi]      = xr * fr - xi * fi;
    qkv[qi + 64] = xr * fi + xi * fr;

    size_t ki = base + (size_t)HH * DD + (size_t)h * DD + d2;
    xr = qkv[ki]; xi = qkv[ki + 64];
    float klo = xr * fr - xi * fi;
    float khi = xr * fi + xi * fr;
    size_t ko = ((size_t)bs * HH + h) * DD + d2;
    out_k[ko]      = klo;
    out_k[ko + 64] = khi;
    size_t kro = (((size_t)(b * HH + h) * SS) + s) * DD + d2;
    kh[kro]      = __float2half_rn(klo);
    kh[kro + 64] = __float2half_rn(khi);

    size_t vi = base + (size_t)2 * HH * DD + (size_t)h * DD + d2;
    out_v[ko]      = qkv[vi];
    out_v[ko + 64] = qkv[vi + 64];
}

// ---------------- V transpose: out_v [B,S,H,D] -> g_vh half [B,H,D,S] -------
__global__ void transpose_v(const float* __restrict__ out_v,
                            __half* __restrict__ vh) {
    __shared__ float t[32][33];
    const int bh = blockIdx.z, b = bh >> 4, h = bh & 15;
    const int s0 = blockIdx.x * 32, d0 = blockIdx.y * 32;
    for (int i = threadIdx.y; i < 32; i += 8)
        t[i][threadIdx.x] =
            out_v[(((size_t)b * SS + s0 + i) * HH + h) * DD + d0 + threadIdx.x];
    __syncthreads();
    for (int i = threadIdx.y; i < 32; i += 8)
        vh[((size_t)bh * DD + d0 + i) * SS + s0 + threadIdx.x] =
            __float2half_rn(t[threadIdx.x][i]);
}

// ============================================================================
// Flash attention, fp16 mma.sync + ldmatrix + 2-stage cp.async K/V prefetch.
// BM=128 (8 warps x 16), BN=64. Causal block skip; heavy tiles scheduled first.
// ============================================================================
#define QSTR 136   // halves
#define VSTR 72    // halves
#define FA_KB   (64 * QSTR)              // K stage, halves
#define FA_VB   (128 * VSTR)             // V stage, halves
#define FA_BYTES ((128*QSTR + 2*FA_KB + 2*FA_VB + 128*VSTR) * 2)  // 124928 B

__global__ __launch_bounds__(256, 1)
void flash_attn(const float* __restrict__ qkv,
                const __half* __restrict__ kh,
                const __half* __restrict__ vh,
                const float* __restrict__ mask,
                __half* __restrict__ attn_out) {
    extern __shared__ __half smh[];
    __half* Qs  = smh;                    // [128][QSTR]
    __half* Ks0 = Qs + 128 * QSTR;        // [2][64][QSTR]
    __half* Vt0 = Ks0 + 2 * FA_KB;        // [2][128][VSTR]
    __half* Ps  = Vt0 + 2 * FA_VB;        // [128][VSTR]

    // heavy (large-qb) tiles first for better makespan
    const int qb = (int)gridDim.x - 1 - (int)blockIdx.x;
    const int h = blockIdx.y, b = blockIdx.z;
    const int tid = threadIdx.x, w = tid >> 5, l = tid & 31;
    const int lr = l >> 2, lc = l & 3;
    const float scale = 0.08838834764831845f;   // 1/sqrt(128)

    const int mat = l >> 3;
    const uint32_t sQ = smem_u32(Qs), sK = smem_u32(Ks0);
    const uint32_t sV = smem_u32(Vt0), sP = smem_u32(Ps);
    const uint32_t qFrag = sQ + (uint32_t)(((w * 16 + (mat & 1) * 8 + (l & 7)) * QSTR)
                                           + (mat >> 1) * 8) * 2;
    const uint32_t kFrag = sK + (uint32_t)((((mat >> 1) * 8 + (l & 7)) * QSTR)
                                           + (mat & 1) * 8) * 2;
    const uint32_t vFrag = sV + (uint32_t)((((mat >> 1) * 8 + (l & 7)) * VSTR)
                                           + (mat & 1) * 8) * 2;
    const uint32_t pFrag = sP + (uint32_t)(((w * 16 + (mat & 1) * 8 + (l & 7)) * VSTR)
                                           + (mat >> 1) * 8) * 2;

    const __half* krh = kh + ((size_t)(b * HH + h) * SS) * DD;
    const __half* vrh = vh + ((size_t)(b * HH + h) * DD) * SS;

    // ---- K/V stage issue via cp.async (8 cp16 per thread) ----
    auto issue_kv = [&](int buf, int kb) {
        const uint32_t kBase = sK + (uint32_t)buf * (FA_KB * 2);
        const uint32_t vBase = sV + (uint32_t)buf * (FA_VB * 2);
#pragma unroll
        for (int j = 0; j < 4; j++) {
            int t = tid + j * 256;              // 1024 chunks of K
            int r = t >> 4, c8 = t & 15;
            cp16(kBase + (uint32_t)(r * QSTR + c8 * 8) * 2,
                 &krh[(size_t)(kb * 64 + r) * DD + c8 * 8]);
        }
#pragma unroll
        for (int j = 0; j < 4; j++) {
            int t = tid + j * 256;              // 1024 chunks of V
            int d = t >> 3, j8 = t & 7;
            cp16(vBase + (uint32_t)(d * VSTR + j8 * 8) * 2,
                 &vrh[(size_t)d * SS + kb * 64 + j8 * 8]);
        }
    };

    // ---- load Q tile (prescaled, half) ----
    for (int t = tid; t < 128 * 32; t += 256) {
        int r = t >> 5, c4 = (t & 31) * 4;
        float4 v = *(const float4*)&qkv[((size_t)b * SS + qb * 128 + r) * QKV_W
                                        + h * DD + c4];
        __half2 h0 = __floats2half2_rn(v.x * scale, v.y * scale);
        __half2 h1 = __floats2half2_rn(v.z * scale, v.w * scale);
        uint2 o = { *(uint32_t*)&h0, *(uint32_t*)&h1 };
        *(uint2*)&Qs[r * QSTR + c4] = o;
    }

    float O[16][4];
#pragma unroll
    for (int nt = 0; nt < 16; nt++)
#pragma unroll
        for (int i = 0; i < 4; i++) O[nt][i] = 0.f;
    float m_lo = -INFINITY, m_hi = -INFINITY, l_lo = 0.f, l_hi = 0.f;

    const int nKV = 2 * qb + 2;

    issue_kv(0, 0);
    CP_COMMIT();

    for (int kb = 0; kb < nKV; kb++) {
        const int buf = kb & 1;
        CP_WAIT0();
        __syncthreads();   // stage kb visible; all reads of stage kb-1 done
        if (kb + 1 < nKV) {
            issue_kv(buf ^ 1, kb + 1);   // overlaps compute of stage kb
            CP_COMMIT();
        }

        const uint32_t kOff = (uint32_t)buf * (FA_KB * 2);
        const uint32_t vOff = (uint32_t)buf * (FA_VB * 2);

        // ---- S = Q K^T : m16 x n64 x k128 per warp (8 k16 steps) ----
        float S[8][4];
#pragma unroll
        for (int nt = 0; nt < 8; nt++)
#pragma unroll
            for (int i = 0; i < 4; i++) S[nt][i] = 0.f;
#pragma unroll
        for (int ks = 0; ks < 8; ks++) {
            uint32_t af[4];
            ldsm_x4(af, qFrag + ks * 32);
#pragma unroll
            for (int p = 0; p < 4; p++) {
                uint32_t r[4];
                ldsm_x4(r, kFrag + kOff + ks * 32 + p * (16 * QSTR * 2));
                mma_f16(S[2 * p], af, r);
                mma_f16(S[2 * p + 1], af, r + 2);
            }
        }

        if (kb >= 2 * qb) {
            const int m_glo = qb * 128 + w * 16 + lr;
            const float* mr0 = &mask[((size_t)b * SS + m_glo) * SS + kb * 64];
            const float* mr1 = mr0 + 8 * SS;
#pragma unroll
            for (int nt = 0; nt < 8; nt++) {
                float2 q0 = *(const float2*)&mr0[nt * 8 + lc * 2];
                float2 q1 = *(const float2*)&mr1[nt * 8 + lc * 2];
                S[nt][0] += q0.x; S[nt][1] += q0.y;
                S[nt][2] += q1.x; S[nt][3] += q1.y;
            }
        }

        float bm_lo = -INFINITY, bm_hi = -INFINITY;
#pragma unroll
        for (int nt = 0; nt < 8; nt++) {
            bm_lo = fmaxf(bm_lo, fmaxf(S[nt][0], S[nt][1]));
            bm_hi = fmaxf(bm_hi, fmaxf(S[nt][2], S[nt][3]));
        }
        bm_lo = fmaxf(bm_lo, __shfl_xor_sync(0xffffffff, bm_lo, 1));
        bm_lo = fmaxf(bm_lo, __shfl_xor_sync(0xffffffff, bm_lo, 2));
        bm_hi = fmaxf(bm_hi, __shfl_xor_sync(0xffffffff, bm_hi, 1));
        bm_hi = fmaxf(bm_hi, __shfl_xor_sync(0xffffffff, bm_hi, 2));
        float mn_lo = fmaxf(m_lo, bm_lo);
        float mn_hi = fmaxf(m_hi, bm_hi);

        float rs_lo = 0.f, rs_hi = 0.f;
#pragma unroll
        for (int nt = 0; nt < 8; nt++) {
            S[nt][0] = __expf(S[nt][0] - mn_lo);
            S[nt][1] = __expf(S[nt][1] - mn_lo);
            S[nt][2] = __expf(S[nt][2] - mn_hi);
            S[nt][3] = __expf(S[nt][3] - mn_hi);
            rs_lo += S[nt][0] + S[nt][1];
            rs_hi += S[nt][2] + S[nt][3];
        }
        rs_lo += __shfl_xor_sync(0xffffffff, rs_lo, 1);
        rs_lo += __shfl_xor_sync(0xffffffff, rs_lo, 2);
        rs_hi += __shfl_xor_sync(0xffffffff, rs_hi, 1);
        rs_hi += __shfl_xor_sync(0xffffffff, rs_hi, 2);

        float al_lo = __expf(m_lo - mn_lo);
        float al_hi = __expf(m_hi - mn_hi);
        l_lo = l_lo * al_lo + rs_lo;
        l_hi = l_hi * al_hi + rs_hi;
        m_lo = mn_lo; m_hi = mn_hi;
#pragma unroll
        for (int nt = 0; nt < 16; nt++) {
            O[nt][0] *= al_lo; O[nt][1] *= al_lo;
            O[nt][2] *= al_hi; O[nt][3] *= al_hi;
        }

        // ---- stage P (warp-local) as half ----
#pragma unroll
        for (int nt = 0; nt < 8; nt++) {
            int cw = nt * 8 + lc * 2;
            __half2 p0 = __floats2half2_rn(S[nt][0], S[nt][1]);
            __half2 p1 = __floats2half2_rn(S[nt][2], S[nt][3]);
            *(__half2*)&Ps[(w * 16 + lr) * VSTR + cw] = p0;
            *(__half2*)&Ps[(w * 16 + lr + 8) * VSTR + cw] = p1;
        }
        __syncwarp();

        // ---- O += P V : m16 x n128 x k64 per warp (4 k16 steps) ----
#pragma unroll
        for (int ks = 0; ks < 4; ks++) {
            uint32_t af[4];
            ldsm_x4(af, pFrag + ks * 32);
#pragma unroll
            for (int p = 0; p < 8; p++) {
                uint32_t r[4];
                ldsm_x4(r, vFrag + vOff + ks * 32 + p * (16 * VSTR * 2));
                mma_f16(O[2 * p], af, r);
                mma_f16(O[2 * p + 1], af, r + 2);
            }
        }
        __syncwarp();
    }

    // epilogue: normalize, write half attn [B,S,H,D]
    const float inv_lo = 1.0f / l_lo, inv_hi = 1.0f / l_hi;
    const int m0 = qb * 128 + w * 16 + lr;
#pragma unroll
    for (int nt = 0; nt < 16; nt++) {
        int d = nt * 8 + lc * 2;
        __half2 v0 = __floats2half2_rn(O[nt][0] * inv_lo, O[nt][1] * inv_lo);
        __half2 v1 = __floats2half2_rn(O[nt][2] * inv_hi, O[nt][3] * inv_hi);
        *(__half2*)&attn_out[(((size_t)b * SS + m0) * HH + h) * DD + d] = v0;
        *(__half2*)&attn_out[(((size_t)b * SS + m0 + 8) * HH + h) * DD + d] = v1;
    }
}

// ---------------- launch ----------------------------------------------------
extern "C" void kernel_launch(void* const* d_in, const int* in_sizes, int n_in,
                              void* d_out, int out_size) {
    const float* x      = (const float*)d_in[0];
    const float* f_r    = (const float*)d_in[1];
    const float* f_i    = (const float*)d_in[2];
    const float* mask   = (const float*)d_in[3];
    const float* W_qkv  = (const float*)d_in[4];
    const float* b_qkv  = (const float*)d_in[5];
    const float* W_o    = (const float*)d_in[6];

    float* out   = (float*)d_out;
    float* out_k = out   + (size_t)BB * SS * NSTATE;
    float* out_v = out_k + (size_t)BB * SS * HH * DD;

    float* qkv = nullptr;    cudaGetSymbolAddress((void**)&qkv,   g_qkv);
    __half* attnh = nullptr; cudaGetSymbolAddress((void**)&attnh, g_attnh);
    __half* xh = nullptr;    cudaGetSymbolAddress((void**)&xh,    g_xh);
    __half* wqh = nullptr;   cudaGetSymbolAddress((void**)&wqh,   g_wqh);
    __half* woh = nullptr;   cudaGetSymbolAddress((void**)&woh,   g_woh);
    __half* kh = nullptr;    cudaGetSymbolAddress((void**)&kh,    g_kh);
    __half* vh = nullptr;    cudaGetSymbolAddress((void**)&vh,    g_vh);

    const int M = BB * SS;   // 4096

    cudaFuncSetAttribute(gemm_mma, cudaFuncAttributeMaxDynamicSharedMemorySize,
                         G_SMEM);
    cudaFuncSetAttribute(flash_attn, cudaFuncAttributeMaxDynamicSharedMemorySize,
                         FA_BYTES);

    // 0) pre-round GEMM inputs to fp16
    {
        int n4x = (M * NSTATE) / 4;
        round_half<<<(n4x + 255) / 256, 256>>>(x, xh, n4x);
        int n4q = (QKV_W * NSTATE) / 4;
        round_half<<<(n4q + 255) / 256, 256>>>(W_qkv, wqh, n4q);
        int n4o = (NSTATE * NSTATE) / 4;
        round_half<<<(n4o + 255) / 256, 256>>>(W_o, woh, n4o);
    }

    // 1) QKV projection (fp16 mma.sync, cp.async 4-stage)
    gemm_mma<<<dim3(QKV_W / 128, M / 128), 256, G_SMEM>>>(
        xh, wqh, b_qkv, qkv, M, QKV_W, NSTATE);
    // 2) RoPE q,k; scatter k,v to output; k half head-major
    rope_scatter<<<(BB * SS * HH * 64) / 256, 256>>>(qkv, f_r, f_i,
                                                     out_k, out_v, kh);
    // 2b) V transpose to [B,H,D,S] half
    transpose_v<<<dim3(SS / 32, DD / 32, BB * HH), dim3(32, 8)>>>(out_v, vh);
    // 3) attention (fp16 mma + ldmatrix + cp.async double-buffer)
    flash_attn<<<dim3(SS / 128, HH, BB), 256, FA_BYTES>>>(qkv, kh, vh,
                                                          mask, attnh);
    // 4) output projection (fp16 mma.sync, cp.async 4-stage)
    gemm_mma<<<dim3(NSTATE / 128, M / 128), 256, G_SMEM>>>(
        attnh, woh, nullptr, out, M, NSTATE, NSTATE);
}

// round 11
// speedup vs baseline: 2.3317x; 1.0412x over previous
#include <cuda_runtime.h>
#include <cuda_fp16.h>
#include <cstdint>
#include <math.h>

// Problem constants
#define BB 2
#define SS 2048
#define HH 16
#define DD 128
#define NSTATE 2048
#define QKV_W (3*HH*DD)   // 6144

// ---------------- scratch (device globals; no runtime alloc) ----------------
__device__ float  g_qkv[(size_t)BB * SS * QKV_W];     // [B,S,6144] fp32
__device__ __half g_attnh[(size_t)BB * SS * HH * DD]; // attn out, half
__device__ __half g_xh[(size_t)BB * SS * NSTATE];     // x half
__device__ __half g_wqh[(size_t)QKV_W * NSTATE];      // W_qkv half
__device__ __half g_woh[(size_t)NSTATE * NSTATE];     // W_o half
__device__ __half g_kh[(size_t)BB * HH * SS * DD];    // k half, [B,H,S,D]
__device__ __half g_vh[(size_t)BB * HH * DD * SS];    // v half, [B,H,D,S]

// ---------------- helpers ----------------------------------------------------
__device__ __forceinline__ uint32_t smem_u32(const void* p) {
    uint32_t a;
    asm("{ .reg .u64 t; cvta.to.shared.u64 t, %1; cvt.u32.u64 %0, t; }"
        : "=r"(a) : "l"(p));
    return a;
}
__device__ __forceinline__ void mma_f16(float* c, const uint32_t* a,
                                        const uint32_t* b) {
    asm volatile(
        "mma.sync.aligned.m16n8k16.row.col.f32.f16.f16.f32 "
        "{%0,%1,%2,%3}, {%4,%5,%6,%7}, {%8,%9}, {%0,%1,%2,%3};\n"
        : "+f"(c[0]), "+f"(c[1]), "+f"(c[2]), "+f"(c[3])
        : "r"(a[0]), "r"(a[1]), "r"(a[2]), "r"(a[3]), "r"(b[0]), "r"(b[1]));
}
__device__ __forceinline__ void ldsm_x4(uint32_t* r, uint32_t addr) {
    asm volatile("ldmatrix.sync.aligned.m8n8.x4.shared.b16 {%0,%1,%2,%3}, [%4];"
                 : "=r"(r[0]), "=r"(r[1]), "=r"(r[2]), "=r"(r[3]) : "r"(addr));
}
__device__ __forceinline__ void cp16(uint32_t s, const void* g) {
    asm volatile("cp.async.cg.shared.global [%0], [%1], 16;"
                 :: "r"(s), "l"(g) : "memory");
}
#define CP_COMMIT() asm volatile("cp.async.commit_group;" ::: "memory")
#define CP_WAIT2()  asm volatile("cp.async.wait_group 2;"  ::: "memory")
#define CP_WAIT0()  asm volatile("cp.async.wait_group 0;"  ::: "memory")

// ---------------- fp32 -> fp16 pre-round pass --------------------------------
__global__ void round_half(const float* __restrict__ src,
                           __half* __restrict__ dst, int n4) {
    int i = blockIdx.x * blockDim.x + threadIdx.x;
    if (i >= n4) return;
    float4 v = ((const float4*)src)[i];
    __half2 h0 = __floats2half2_rn(v.x, v.y);
    __half2 h1 = __floats2half2_rn(v.z, v.w);
    uint2 o = { *(uint32_t*)&h0, *(uint32_t*)&h1 };
    ((uint2*)dst)[i] = o;
}

// ============================================================================
// fp16 mma.sync GEMM (NT): C[m,n] = sum_k A[m,k]*B[n,k] (+bias[n]), fp32 acc
// Block 128x128, BK=32 halves, 8 warps (4x2), warp tile 32x64,
// 4-stage cp.async ring, TPH=40 rows, ldmatrix, A-frags hoisted for ILP.
// ============================================================================
#define TPH 40                                // halves; 80B row (5x16B, odd)
#define G_NSTG 4
#define G_AB (128 * TPH * 2)                  // 10240 B per operand tile
#define G_STG (2 * G_AB)                      // 20480 B per stage
#define G_SMEM (G_NSTG * G_STG)               // 81920 B

__device__ __forceinline__ void gemm_issue(uint32_t sbase,
                                           const __half* __restrict__ A,
                                           const __half* __restrict__ B,
                                           int m0, int n0, int K, int k0,
                                           int tid) {
    const int row = tid >> 2, seg = tid & 3;     // 64 rows x 4 segs per pass
    cp16(sbase + (uint32_t)(row * TPH + seg * 8) * 2,
         &A[(size_t)(m0 + row) * K + k0 + seg * 8]);
    cp16(sbase + (uint32_t)((row + 64) * TPH + seg * 8) * 2,
         &A[(size_t)(m0 + row + 64) * K + k0 + seg * 8]);
    const uint32_t sB = sbase + G_AB;
    cp16(sB + (uint32_t)(row * TPH + seg * 8) * 2,
         &B[(size_t)(n0 + row) * K + k0 + seg * 8]);
    cp16(sB + (uint32_t)((row + 64) * TPH + seg * 8) * 2,
         &B[(size_t)(n0 + row + 64) * K + k0 + seg * 8]);
}

__global__ __launch_bounds__(256, 2)
void gemm_mma(const __half* __restrict__ A, const __half* __restrict__ B,
              const float* __restrict__ bias, float* __restrict__ C,
              int M, int N, int K) {
    extern __shared__ uint32_t dynsm[];
    const uint32_t sb = smem_u32(dynsm);

    const int tid = threadIdx.x;
    const int w = tid >> 5, l = tid & 31;
    const int lr = l >> 2, lc = l & 3;
    const int wm = w >> 1, wn = w & 1;           // 4 (m) x 2 (n)
    const int m0 = blockIdx.y * 128, n0 = blockIdx.x * 128;
    const int mat = l >> 3;

    const uint32_t aOff = (uint32_t)(((wm * 32 + (mat & 1) * 8 + (l & 7)) * TPH)
                                     + (mat >> 1) * 8) * 2;
    const uint32_t bOff = G_AB
                        + (uint32_t)(((wn * 64 + (mat >> 1) * 8 + (l & 7)) * TPH)
                                     + (mat & 1) * 8) * 2;

    float acc[2][8][4];
#pragma unroll
    for (int mt = 0; mt < 2; mt++)
#pragma unroll
        for (int nt = 0; nt < 8; nt++)
#pragma unroll
            for (int i = 0; i < 4; i++) acc[mt][nt][i] = 0.f;

    const int NC = K / 32;

#pragma unroll
    for (int s = 0; s < G_NSTG - 1; s++) {
        gemm_issue(sb + s * G_STG, A, B, m0, n0, K, s * 32, tid);
        CP_COMMIT();
    }

    for (int c = 0; c < NC; c++) {
        CP_WAIT2();
        __syncthreads();

        const int nc = c + G_NSTG - 1;
        if (nc < NC)
            gemm_issue(sb + (nc % G_NSTG) * G_STG, A, B, m0, n0, K, nc * 32, tid);
        CP_COMMIT();

        const uint32_t st = sb + (c % G_NSTG) * G_STG;
        // hoist all A fragments (both k16 sub-steps) for ILP
        uint32_t af[2][2][4];                  // [kk][mt]
#pragma unroll
        for (int kk = 0; kk < 2; kk++) {
            ldsm_x4(af[kk][0], st + aOff + kk * 32);
            ldsm_x4(af[kk][1], st + aOff + kk * 32 + 16 * TPH * 2);
        }
#pragma unroll
        for (int p = 0; p < 4; p++) {
            uint32_t r0[4], r1[4];
            ldsm_x4(r0, st + bOff + p * (16 * TPH * 2));
            ldsm_x4(r1, st + bOff + 32 + p * (16 * TPH * 2));
#pragma unroll
            for (int mt = 0; mt < 2; mt++) {
                mma_f16(acc[mt][2 * p],     af[0][mt], r0);
                mma_f16(acc[mt][2 * p + 1], af[0][mt], r0 + 2);
                mma_f16(acc[mt][2 * p],     af[1][mt], r1);
                mma_f16(acc[mt][2 * p + 1], af[1][mt], r1 + 2);
            }
        }
    }

#pragma unroll
    for (int mt = 0; mt < 2; mt++) {
        int m = m0 + wm * 32 + mt * 16 + lr;
#pragma unroll
        for (int nt = 0; nt < 8; nt++) {
            int n = n0 + wn * 64 + nt * 8 + lc * 2;
            float bx = 0.f, by = 0.f;
            if (bias) { bx = bias[n]; by = bias[n + 1]; }
            float2 v0 = { acc[mt][nt][0] + bx, acc[mt][nt][1] + by };
            float2 v1 = { acc[mt][nt][2] + bx, acc[mt][nt][3] + by };
            *(float2*)&C[(size_t)m * N + n] = v0;
            *(float2*)&C[(size_t)(m + 8) * N + n] = v1;
        }
    }
}

// ---------------- RoPE: q in place; k -> out_k (fp32) + g_kh (half, head-major)
__global__ void rope_scatter(float* __restrict__ qkv,
                             const float* __restrict__ f_r,
                             const float* __restrict__ f_i,
                             float* __restrict__ out_k,
                             float* __restrict__ out_v,
                             __half* __restrict__ kh) {
    int idx = blockIdx.x * blockDim.x + threadIdx.x;
    if (idx >= BB * SS * HH * 64) return;
    int d2 = idx & 63;
    int h  = (idx >> 6) & (HH - 1);
    int bs = idx >> 10;
    int b = bs >> 11, s = bs & (SS - 1);

    float fr = f_r[(size_t)bs * 64 + d2];
    float fi = f_i[(size_t)bs * 64 + d2];

    size_t base = (size_t)bs * QKV_W;
    size_t qi = base + (size_t)h * DD + d2;
    float xr = qkv[qi], xi = qkv[qi + 64];
    qkv[qi]      = xr * fr - xi * fi;
    qkv[qi + 64] = xr * fi + xi * fr;

    size_t ki = base + (size_t)HH * DD + (size_t)h * DD + d2;
    xr = qkv[ki]; xi = qkv[ki + 64];
    float klo = xr * fr - xi * fi;
    float khi = xr * fi + xi * fr;
    size_t ko = ((size_t)bs * HH + h) * DD + d2;
    out_k[ko]      = klo;
    out_k[ko + 64] = khi;
    size_t kro = (((size_t)(b * HH + h) * SS) + s) * DD + d2;
    kh[kro]      = __float2half_rn(klo);
    kh[kro + 64] = __float2half_rn(khi);

    size_t vi = base + (size_t)2 * HH * DD + (size_t)h * DD + d2;
    out_v[ko]      = qkv[vi];
    out_v[ko + 64] = qkv[vi + 64];
}

// ---------------- V transpose: out_v [B,S,H,D] -> g_vh half [B,H,D,S] -------
__global__ void transpose_v(const float* __restrict__ out_v,
                            __half* __restrict__ vh) {
    __shared__ float t[32][33];
    const int bh = blockIdx.z, b = bh >> 4, h = bh & 15;
    const int s0 = blockIdx.x * 32, d0 = blockIdx.y * 32;
    for (int i = threadIdx.y; i < 32; i += 8)
        t[i][threadIdx.x] =
            out_v[(((size_t)b * SS + s0 + i) * HH + h) * DD + d0 + threadIdx.x];
    __syncthreads();
    for (int i = threadIdx.y; i < 32; i += 8)
        vh[((size_t)bh * DD + d0 + i) * SS + s0 + threadIdx.x] =
            __float2half_rn(t[threadIdx.x][i]);
}

// ============================================================================
// Flash attention, fp16 mma.sync + ldmatrix + 2-stage cp.async K/V prefetch.
// BM=128 (8 warps x 16), BN=128 kv per block. Causal block skip; heavy first.
// ============================================================================
#define FSTR 136   // halves: row stride for Q/K/V/P tiles (272B, odd 16B count)
#define FA_KB   (128 * FSTR)             // K stage, halves
#define FA_VB   (128 * FSTR)             // V stage, halves
#define FA_BYTES ((128*FSTR /*Q*/ + 2*FA_KB + 2*FA_VB + 128*FSTR /*P*/) * 2) // 208896

__global__ __launch_bounds__(256, 1)
void flash_attn(const float* __restrict__ qkv,
                const __half* __restrict__ kh,
                const __half* __restrict__ vh,
                const float* __restrict__ mask,
                __half* __restrict__ attn_out) {
    extern __shared__ __half smh[];
    __half* Qs  = smh;                    // [128][FSTR]
    __half* Ks0 = Qs + 128 * FSTR;        // [2][128][FSTR]
    __half* Vt0 = Ks0 + 2 * FA_KB;        // [2][128][FSTR]  (V transposed [d][j])
    __half* Ps  = Vt0 + 2 * FA_VB;        // [128][FSTR]

    // heavy (large-qb) tiles first for better makespan
    const int qb = (int)gridDim.x - 1 - (int)blockIdx.x;
    const int h = blockIdx.y, b = blockIdx.z;
    const int tid = threadIdx.x, w = tid >> 5, l = tid & 31;
    const int lr = l >> 2, lc = l & 3;
    const float scale = 0.08838834764831845f;   // 1/sqrt(128)

    const int mat = l >> 3;
    const uint32_t sQ = smem_u32(Qs), sK = smem_u32(Ks0);
    const uint32_t sV = smem_u32(Vt0), sP = smem_u32(Ps);
    const uint32_t qFrag = sQ + (uint32_t)(((w * 16 + (mat & 1) * 8 + (l & 7)) * FSTR)
                                           + (mat >> 1) * 8) * 2;
    const uint32_t kFrag = sK + (uint32_t)((((mat >> 1) * 8 + (l & 7)) * FSTR)
                                           + (mat & 1) * 8) * 2;
    const uint32_t vFrag = sV + (uint32_t)((((mat >> 1) * 8 + (l & 7)) * FSTR)
                                           + (mat & 1) * 8) * 2;
    const uint32_t pFrag = sP + (uint32_t)(((w * 16 + (mat & 1) * 8 + (l & 7)) * FSTR)
                                           + (mat >> 1) * 8) * 2;

    const __half* krh = kh + ((size_t)(b * HH + h) * SS) * DD;
    const __half* vrh = vh + ((size_t)(b * HH + h) * DD) * SS;

    // ---- K/V stage issue via cp.async (16 cp16 per thread) ----
    auto issue_kv = [&](int buf, int kb) {
        const uint32_t kBase = sK + (uint32_t)buf * (FA_KB * 2);
        const uint32_t vBase = sV + (uint32_t)buf * (FA_VB * 2);
#pragma unroll
        for (int j = 0; j < 8; j++) {
            int t = tid + j * 256;              // 2048 chunks of K
            int r = t >> 4, c8 = t & 15;
            cp16(kBase + (uint32_t)(r * FSTR + c8 * 8) * 2,
                 &krh[(size_t)(kb * 128 + r) * DD + c8 * 8]);
        }
#pragma unroll
        for (int j = 0; j < 8; j++) {
            int t = tid + j * 256;              // 2048 chunks of V
            int d = t >> 4, j8 = t & 15;
            cp16(vBase + (uint32_t)(d * FSTR + j8 * 8) * 2,
                 &vrh[(size_t)d * SS + kb * 128 + j8 * 8]);
        }
    };

    // ---- load Q tile (prescaled, half) ----
    for (int t = tid; t < 128 * 32; t += 256) {
        int r = t >> 5, c4 = (t & 31) * 4;
        float4 v = *(const float4*)&qkv[((size_t)b * SS + qb * 128 + r) * QKV_W
                                        + h * DD + c4];
        __half2 h0 = __floats2half2_rn(v.x * scale, v.y * scale);
        __half2 h1 = __floats2half2_rn(v.z * scale, v.w * scale);
        uint2 o = { *(uint32_t*)&h0, *(uint32_t*)&h1 };
        *(uint2*)&Qs[r * FSTR + c4] = o;
    }

    float O[16][4];
#pragma unroll
    for (int nt = 0; nt < 16; nt++)
#pragma unroll
        for (int i = 0; i < 4; i++) O[nt][i] = 0.f;
    float m_lo = -INFINITY, m_hi = -INFINITY, l_lo = 0.f, l_hi = 0.f;

    const int nKV = qb + 1;                 // causal, 128-wide kv blocks

    issue_kv(0, 0);
    CP_COMMIT();

    for (int kb = 0; kb < nKV; kb++) {
        const int buf = kb & 1;
        CP_WAIT0();
        __syncthreads();   // stage kb visible; all reads of stage kb-1 done
        if (kb + 1 < nKV) {
            issue_kv(buf ^ 1, kb + 1);   // overlaps compute of stage kb
            CP_COMMIT();
        }

        const uint32_t kOff = (uint32_t)buf * (FA_KB * 2);
        const uint32_t vOff = (uint32_t)buf * (FA_VB * 2);

        // ---- S = Q K^T : m16 x n128 x k128 per warp (8 k16 steps) ----
        float S[16][4];
#pragma unroll
        for (int nt = 0; nt < 16; nt++)
#pragma unroll
            for (int i = 0; i < 4; i++) S[nt][i] = 0.f;
#pragma unroll
        for (int ks = 0; ks < 8; ks++) {
            uint32_t af[4];
            ldsm_x4(af, qFrag + ks * 32);
#pragma unroll
            for (int p = 0; p < 8; p++) {
                uint32_t r[4];
                ldsm_x4(r, kFrag + kOff + ks * 32 + p * (16 * FSTR * 2));
                mma_f16(S[2 * p], af, r);
                mma_f16(S[2 * p + 1], af, r + 2);
            }
        }

        // ---- diagonal block: add gmem mask ----
        if (kb == qb) {
            const int m_glo = qb * 128 + w * 16 + lr;
            const float* mr0 = &mask[((size_t)b * SS + m_glo) * SS + kb * 128];
            const float* mr1 = mr0 + 8 * SS;
#pragma unroll
            for (int nt = 0; nt < 16; nt++) {
                float2 q0 = *(const float2*)&mr0[nt * 8 + lc * 2];
                float2 q1 = *(const float2*)&mr1[nt * 8 + lc * 2];
                S[nt][0] += q0.x; S[nt][1] += q0.y;
                S[nt][2] += q1.x; S[nt][3] += q1.y;
            }
        }

        // ---- online softmax (rows lr and lr+8) ----
        float bm_lo = -INFINITY, bm_hi = -INFINITY;
#pragma unroll
        for (int nt = 0; nt < 16; nt++) {
            bm_lo = fmaxf(bm_lo, fmaxf(S[nt][0], S[nt][1]));
            bm_hi = fmaxf(bm_hi, fmaxf(S[nt][2], S[nt][3]));
        }
        bm_lo = fmaxf(bm_lo, __shfl_xor_sync(0xffffffff, bm_lo, 1));
        bm_lo = fmaxf(bm_lo, __shfl_xor_sync(0xffffffff, bm_lo, 2));
        bm_hi = fmaxf(bm_hi, __shfl_xor_sync(0xffffffff, bm_hi, 1));
        bm_hi = fmaxf(bm_hi, __shfl_xor_sync(0xffffffff, bm_hi, 2));
        float mn_lo = fmaxf(m_lo, bm_lo);
        float mn_hi = fmaxf(m_hi, bm_hi);

        float rs_lo = 0.f, rs_hi = 0.f;
#pragma unroll
        for (int nt = 0; nt < 16; nt++) {
            S[nt][0] = __expf(S[nt][0] - mn_lo);
            S[nt][1] = __expf(S[nt][1] - mn_lo);
            S[nt][2] = __expf(S[nt][2] - mn_hi);
            S[nt][3] = __expf(S[nt][3] - mn_hi);
            rs_lo += S[nt][0] + S[nt][1];
            rs_hi += S[nt][2] + S[nt][3];
        }
        rs_lo += __shfl_xor_sync(0xffffffff, rs_lo, 1);
        rs_lo += __shfl_xor_sync(0xffffffff, rs_lo, 2);
        rs_hi += __shfl_xor_sync(0xffffffff, rs_hi, 1);
        rs_hi += __shfl_xor_sync(0xffffffff, rs_hi, 2);

        float al_lo = __expf(m_lo - mn_lo);
        float al_hi = __expf(m_hi - mn_hi);
        l_lo = l_lo * al_lo + rs_lo;
        l_hi = l_hi * al_hi + rs_hi;
        m_lo = mn_lo; m_hi = mn_hi;
#pragma unroll
        for (int nt = 0; nt < 16; nt++) {
            O[nt][0] *= al_lo; O[nt][1] *= al_lo;
            O[nt][2] *= al_hi; O[nt][3] *= al_hi;
        }

        // ---- stage P (warp-local) as half ----
#pragma unroll
        for (int nt = 0; nt < 16; nt++) {
            int cw = nt * 8 + lc * 2;
            __half2 p0 = __floats2half2_rn(S[nt][0], S[nt][1]);
            __half2 p1 = __floats2half2_rn(S[nt][2], S[nt][3]);
            *(__half2*)&Ps[(w * 16 + lr) * FSTR + cw] = p0;
            *(__half2*)&Ps[(w * 16 + lr + 8) * FSTR + cw] = p1;
        }
        __syncwarp();

        // ---- O += P V : m16 x n128 x k128 per warp (8 k16 steps) ----
#pragma unroll
        for (int ks = 0; ks < 8; ks++) {
            uint32_t af[4];
            ldsm_x4(af, pFrag + ks * 32);
#pragma unroll
            for (int p = 0; p < 8; p++) {
                uint32_t r[4];
                ldsm_x4(r, vFrag + vOff + ks * 32 + p * (16 * FSTR * 2));
                mma_f16(O[2 * p], af, r);
                mma_f16(O[2 * p + 1], af, r + 2);
            }
        }
        __syncwarp();
    }

    // epilogue: normalize, write half attn [B,S,H,D]
    const float inv_lo = 1.0f / l_lo, inv_hi = 1.0f / l_hi;
    const int m0 = qb * 128 + w * 16 + lr;
#pragma unroll
    for (int nt = 0; nt < 16; nt++) {
        int d = nt * 8 + lc * 2;
        __half2 v0 = __floats2half2_rn(O[nt][0] * inv_lo, O[nt][1] * inv_lo);
        __half2 v1 = __floats2half2_rn(O[nt][2] * inv_hi, O[nt][3] * inv_hi);
        *(__half2*)&attn_out[(((size_t)b * SS + m0) * HH + h) * DD + d] = v0;
        *(__half2*)&attn_out[(((size_t)b * SS + m0 + 8) * HH + h) * DD + d] = v1;
    }
}

// ---------------- launch ----------------------------------------------------
extern "C" void kernel_launch(void* const* d_in, const int* in_sizes, int n_in,
                              void* d_out, int out_size) {
    const float* x      = (const float*)d_in[0];
    const float* f_r    = (const float*)d_in[1];
    const float* f_i    = (const float*)d_in[2];
    const float* mask   = (const float*)d_in[3];
    const float* W_qkv  = (const float*)d_in[4];
    const float* b_qkv  = (const float*)d_in[5];
    const float* W_o    = (const float*)d_in[6];

    float* out   = (float*)d_out;
    float* out_k = out   + (size_t)BB * SS * NSTATE;
    float* out_v = out_k + (size_t)BB * SS * HH * DD;

    float* qkv = nullptr;    cudaGetSymbolAddress((void**)&qkv,   g_qkv);
    __half* attnh = nullptr; cudaGetSymbolAddress((void**)&attnh, g_attnh);
    __half* xh = nullptr;    cudaGetSymbolAddress((void**)&xh,    g_xh);
    __half* wqh = nullptr;   cudaGetSymbolAddress((void**)&wqh,   g_wqh);
    __half* woh = nullptr;   cudaGetSymbolAddress((void**)&woh,   g_woh);
    __half* kh = nullptr;    cudaGetSymbolAddress((void**)&kh,    g_kh);
    __half* vh = nullptr;    cudaGetSymbolAddress((void**)&vh,    g_vh);

    const int M = BB * SS;   // 4096

    cudaFuncSetAttribute(gemm_mma, cudaFuncAttributeMaxDynamicSharedMemorySize,
                         G_SMEM);
    cudaFuncSetAttribute(flash_attn, cudaFuncAttributeMaxDynamicSharedMemorySize,
                         FA_BYTES);

    // 0) pre-round GEMM inputs to fp16
    {
        int n4x = (M * NSTATE) / 4;
        round_half<<<(n4x + 255) / 256, 256>>>(x, xh, n4x);
        int n4q = (QKV_W * NSTATE) / 4;
        round_half<<<(n4q + 255) / 256, 256>>>(W_qkv, wqh, n4q);
        int n4o = (NSTATE * NSTATE) / 4;
        round_half<<<(n4o + 255) / 256, 256>>>(W_o, woh, n4o);
    }

    // 1) QKV projection (fp16 mma.sync, cp.async 4-stage)
    gemm_mma<<<dim3(QKV_W / 128, M / 128), 256, G_SMEM>>>(
        xh, wqh, b_qkv, qkv, M, QKV_W, NSTATE);
    // 2) RoPE q,k; scatter k,v to output; k half head-major
    rope_scatter<<<(BB * SS * HH * 64) / 256, 256>>>(qkv, f_r, f_i,
                                                     out_k, out_v, kh);
    // 2b) V transpose to [B,H,D,S] half
    transpose_v<<<dim3(SS / 32, DD / 32, BB * HH), dim3(32, 8)>>>(out_v, vh);
    // 3) attention (fp16 mma + ldmatrix + cp.async double-buffer, BN=128)
    flash_attn<<<dim3(SS / 128, HH, BB), 256, FA_BYTES>>>(qkv, kh, vh,
                                                          mask, attnh);
    // 4) output projection (fp16 mma.sync, cp.async 4-stage)
    gemm_mma<<<dim3(NSTATE / 128, M / 128), 256, G_SMEM>>>(
        attnh, woh, nullptr, out, M, NSTATE, NSTATE);
}

// round 12
// speedup vs baseline: 2.5406x; 1.0896x over previous
#include <cuda_runtime.h>
#include <cuda_fp16.h>
#include <cstdint>
#include <math.h>

// Problem constants
#define BB 2
#define SS 2048
#define HH 16
#define DD 128
#define NSTATE 2048
#define QKV_W (3*HH*DD)   // 6144

// ---------------- scratch (device globals; no runtime alloc) ----------------
__device__ float  g_qkv[(size_t)BB * SS * QKV_W];     // [B,S,6144] fp32
__device__ __half g_attnh[(size_t)BB * SS * HH * DD]; // attn out, half
__device__ __half g_xh[(size_t)BB * SS * NSTATE];     // x half
__device__ __half g_wqh[(size_t)QKV_W * NSTATE];      // W_qkv half
__device__ __half g_woh[(size_t)NSTATE * NSTATE];     // W_o half
__device__ __half g_kh[(size_t)BB * HH * SS * DD];    // k half, [B,H,S,D]
__device__ __half g_vh[(size_t)BB * HH * DD * SS];    // v half, [B,H,D,S]

// ---------------- helpers ----------------------------------------------------
__device__ __forceinline__ uint32_t smem_u32(const void* p) {
    uint32_t a;
    asm("{ .reg .u64 t; cvta.to.shared.u64 t, %1; cvt.u32.u64 %0, t; }"
        : "=r"(a) : "l"(p));
    return a;
}
__device__ __forceinline__ void mma_f16(float* c, const uint32_t* a,
                                        const uint32_t* b) {
    asm volatile(
        "mma.sync.aligned.m16n8k16.row.col.f32.f16.f16.f32 "
        "{%0,%1,%2,%3}, {%4,%5,%6,%7}, {%8,%9}, {%0,%1,%2,%3};\n"
        : "+f"(c[0]), "+f"(c[1]), "+f"(c[2]), "+f"(c[3])
        : "r"(a[0]), "r"(a[1]), "r"(a[2]), "r"(a[3]), "r"(b[0]), "r"(b[1]));
}
__device__ __forceinline__ void ldsm_x4(uint32_t* r, uint32_t addr) {
    asm volatile("ldmatrix.sync.aligned.m8n8.x4.shared.b16 {%0,%1,%2,%3}, [%4];"
                 : "=r"(r[0]), "=r"(r[1]), "=r"(r[2]), "=r"(r[3]) : "r"(addr));
}
__device__ __forceinline__ void cp16(uint32_t s, const void* g) {
    asm volatile("cp.async.cg.shared.global [%0], [%1], 16;"
                 :: "r"(s), "l"(g) : "memory");
}
__device__ __forceinline__ uint32_t h2bits(__half2 h) {
    return *(uint32_t*)&h;
}
#define CP_COMMIT() asm volatile("cp.async.commit_group;" ::: "memory")
#define CP_WAIT2()  asm volatile("cp.async.wait_group 2;"  ::: "memory")
#define CP_WAIT0()  asm volatile("cp.async.wait_group 0;"  ::: "memory")

// ---------------- fp32 -> fp16 pre-round pass --------------------------------
__global__ void round_half(const float* __restrict__ src,
                           __half* __restrict__ dst, int n4) {
    int i = blockIdx.x * blockDim.x + threadIdx.x;
    if (i >= n4) return;
    float4 v = ((const float4*)src)[i];
    __half2 h0 = __floats2half2_rn(v.x, v.y);
    __half2 h1 = __floats2half2_rn(v.z, v.w);
    uint2 o = { *(uint32_t*)&h0, *(uint32_t*)&h1 };
    ((uint2*)dst)[i] = o;
}

// ============================================================================
// fp16 mma.sync GEMM (NT): C[m,n] = sum_k A[m,k]*B[n,k] (+bias[n]), fp32 acc
// Block 128x128, BK=32 halves, 4 warps (2x2), warp tile 64x64,
// 4-stage cp.async ring, TPH=40 rows, ldmatrix. 2 CTAs/SM (128 thr each).
// ============================================================================
#define TPH 40                                // halves; 80B row (5x16B, odd)
#define G_NSTG 4
#define G_AB (128 * TPH * 2)                  // 10240 B per operand tile
#define G_STG (2 * G_AB)                      // 20480 B per stage
#define G_SMEM (G_NSTG * G_STG)               // 81920 B

__device__ __forceinline__ void gemm_issue(uint32_t sbase,
                                           const __half* __restrict__ A,
                                           const __half* __restrict__ B,
                                           int m0, int n0, int K, int k0,
                                           int tid) {
#pragma unroll
    for (int j = 0; j < 4; j++) {               // 512 chunks of A
        int t = tid + j * 128;
        int row = t >> 2, seg = t & 3;
        cp16(sbase + (uint32_t)(row * TPH + seg * 8) * 2,
             &A[(size_t)(m0 + row) * K + k0 + seg * 8]);
    }
    const uint32_t sB = sbase + G_AB;
#pragma unroll
    for (int j = 0; j < 4; j++) {               // 512 chunks of B
        int t = tid + j * 128;
        int row = t >> 2, seg = t & 3;
        cp16(sB + (uint32_t)(row * TPH + seg * 8) * 2,
             &B[(size_t)(n0 + row) * K + k0 + seg * 8]);
    }
}

__global__ __launch_bounds__(128, 2)
void gemm_mma(const __half* __restrict__ A, const __half* __restrict__ B,
              const float* __restrict__ bias, float* __restrict__ C,
              int M, int N, int K) {
    extern __shared__ uint32_t dynsm[];
    const uint32_t sb = smem_u32(dynsm);

    const int tid = threadIdx.x;
    const int w = tid >> 5, l = tid & 31;
    const int lr = l >> 2, lc = l & 3;
    const int wm = w >> 1, wn = w & 1;           // 2 (m) x 2 (n)
    const int m0 = blockIdx.y * 128, n0 = blockIdx.x * 128;
    const int mat = l >> 3;

    const uint32_t aOff = (uint32_t)(((wm * 64 + (mat & 1) * 8 + (l & 7)) * TPH)
                                     + (mat >> 1) * 8) * 2;
    const uint32_t bOff = G_AB
                        + (uint32_t)(((wn * 64 + (mat >> 1) * 8 + (l & 7)) * TPH)
                                     + (mat & 1) * 8) * 2;

    float acc[4][8][4];
#pragma unroll
    for (int mt = 0; mt < 4; mt++)
#pragma unroll
        for (int nt = 0; nt < 8; nt++)
#pragma unroll
            for (int i = 0; i < 4; i++) acc[mt][nt][i] = 0.f;

    const int NC = K / 32;

#pragma unroll
    for (int s = 0; s < G_NSTG - 1; s++) {
        gemm_issue(sb + s * G_STG, A, B, m0, n0, K, s * 32, tid);
        CP_COMMIT();
    }

    for (int c = 0; c < NC; c++) {
        CP_WAIT2();
        __syncthreads();

        const int nc = c + G_NSTG - 1;
        if (nc < NC)
            gemm_issue(sb + (nc % G_NSTG) * G_STG, A, B, m0, n0, K, nc * 32, tid);
        CP_COMMIT();

        const uint32_t st = sb + (c % G_NSTG) * G_STG;
#pragma unroll
        for (int kk = 0; kk < 2; kk++) {
            uint32_t af[4][4];
#pragma unroll
            for (int mt = 0; mt < 4; mt++)
                ldsm_x4(af[mt], st + aOff + kk * 32 + mt * (16 * TPH * 2));
#pragma unroll
            for (int p = 0; p < 4; p++) {
                uint32_t r[4];
                ldsm_x4(r, st + bOff + kk * 32 + p * (16 * TPH * 2));
#pragma unroll
                for (int mt = 0; mt < 4; mt++) {
                    mma_f16(acc[mt][2 * p],     af[mt], r);
                    mma_f16(acc[mt][2 * p + 1], af[mt], r + 2);
                }
            }
        }
    }

#pragma unroll
    for (int mt = 0; mt < 4; mt++) {
        int m = m0 + wm * 64 + mt * 16 + lr;
#pragma unroll
        for (int nt = 0; nt < 8; nt++) {
            int n = n0 + wn * 64 + nt * 8 + lc * 2;
            float bx = 0.f, by = 0.f;
            if (bias) { bx = bias[n]; by = bias[n + 1]; }
            float2 v0 = { acc[mt][nt][0] + bx, acc[mt][nt][1] + by };
            float2 v1 = { acc[mt][nt][2] + bx, acc[mt][nt][3] + by };
            *(float2*)&C[(size_t)m * N + n] = v0;
            *(float2*)&C[(size_t)(m + 8) * N + n] = v1;
        }
    }
}

// ---------------- RoPE: q in place; k -> out_k (fp32) + g_kh (half, head-major)
__global__ void rope_scatter(float* __restrict__ qkv,
                             const float* __restrict__ f_r,
                             const float* __restrict__ f_i,
                             float* __restrict__ out_k,
                             float* __restrict__ out_v,
                             __half* __restrict__ kh) {
    int idx = blockIdx.x * blockDim.x + threadIdx.x;
    if (idx >= BB * SS * HH * 64) return;
    int d2 = idx & 63;
    int h  = (idx >> 6) & (HH - 1);
    int bs = idx >> 10;
    int b = bs >> 11, s = bs & (SS - 1);

    float fr = f_r[(size_t)bs * 64 + d2];
    float fi = f_i[(size_t)bs * 64 + d2];

    size_t base = (size_t)bs * QKV_W;
    size_t qi = base + (size_t)h * DD + d2;
    float xr = qkv[qi], xi = qkv[qi + 64];
    qkv[qi]      = xr * fr - xi * fi;
    qkv[qi + 64] = xr * fi + xi * fr;

    size_t ki = base + (size_t)HH * DD + (size_t)h * DD + d2;
    xr = qkv[ki]; xi = qkv[ki + 64];
    float klo = xr * fr - xi * fi;
    float khi = xr * fi + xi * fr;
    size_t ko = ((size_t)bs * HH + h) * DD + d2;
    out_k[ko]      = klo;
    out_k[ko + 64] = khi;
    size_t kro = (((size_t)(b * HH + h) * SS) + s) * DD + d2;
    kh[kro]      = __float2half_rn(klo);
    kh[kro + 64] = __float2half_rn(khi);

    size_t vi = base + (size_t)2 * HH * DD + (size_t)h * DD + d2;
    out_v[ko]      = qkv[vi];
    out_v[ko + 64] = qkv[vi + 64];
}

// ---------------- V transpose: out_v [B,S,H,D] -> g_vh half [B,H,D,S] -------
__global__ void transpose_v(const float* __restrict__ out_v,
                            __half* __restrict__ vh) {
    __shared__ float t[32][33];
    const int bh = blockIdx.z, b = bh >> 4, h = bh & 15;
    const int s0 = blockIdx.x * 32, d0 = blockIdx.y * 32;
    for (int i = threadIdx.y; i < 32; i += 8)
        t[i][threadIdx.x] =
            out_v[(((size_t)b * SS + s0 + i) * HH + h) * DD + d0 + threadIdx.x];
    __syncthreads();
    for (int i = threadIdx.y; i < 32; i += 8)
        vh[((size_t)bh * DD + d0 + i) * SS + s0 + threadIdx.x] =
            __float2half_rn(t[threadIdx.x][i]);
}

// ============================================================================
// Flash attention, fp16 mma.sync + ldmatrix + 2-stage cp.async K/V prefetch.
// BM=128 (8 warps x 16), BN=128. Q fragments hoisted to registers; P stays in
// registers (S-accumulator fragment == PV A-fragment). Causal; heavy first.
// ============================================================================
#define FSTR 136   // halves: row stride (272B, odd 16B count)
#define FA_KB   (128 * FSTR)             // K stage, halves
#define FA_VB   (128 * FSTR)             // V stage, halves
#define FA_BYTES ((128*FSTR /*Q*/ + 2*FA_KB + 2*FA_VB) * 2)   // 174080 B

__global__ __launch_bounds__(256, 1)
void flash_attn(const float* __restrict__ qkv,
                const __half* __restrict__ kh,
                const __half* __restrict__ vh,
                const float* __restrict__ mask,
                __half* __restrict__ attn_out) {
    extern __shared__ __half smh[];
    __half* Qs  = smh;                    // [128][FSTR]
    __half* Ks0 = Qs + 128 * FSTR;        // [2][128][FSTR]
    __half* Vt0 = Ks0 + 2 * FA_KB;        // [2][128][FSTR]  (V transposed [d][j])

    // heavy (large-qb) tiles first for better makespan
    const int qb = (int)gridDim.x - 1 - (int)blockIdx.x;
    const int h = blockIdx.y, b = blockIdx.z;
    const int tid = threadIdx.x, w = tid >> 5, l = tid & 31;
    const int lr = l >> 2, lc = l & 3;
    const float scale = 0.08838834764831845f;   // 1/sqrt(128)

    const int mat = l >> 3;
    const uint32_t sQ = smem_u32(Qs), sK = smem_u32(Ks0);
    const uint32_t sV = smem_u32(Vt0);
    const uint32_t qFrag = sQ + (uint32_t)(((w * 16 + (mat & 1) * 8 + (l & 7)) * FSTR)
                                           + (mat >> 1) * 8) * 2;
    const uint32_t kFrag = sK + (uint32_t)((((mat >> 1) * 8 + (l & 7)) * FSTR)
                                           + (mat & 1) * 8) * 2;
    const uint32_t vFrag = sV + (uint32_t)((((mat >> 1) * 8 + (l & 7)) * FSTR)
                                           + (mat & 1) * 8) * 2;

    const __half* krh = kh + ((size_t)(b * HH + h) * SS) * DD;
    const __half* vrh = vh + ((size_t)(b * HH + h) * DD) * SS;

    // ---- K/V stage issue via cp.async (16 cp16 per thread) ----
    auto issue_kv = [&](int buf, int kb) {
        const uint32_t kBase = sK + (uint32_t)buf * (FA_KB * 2);
        const uint32_t vBase = sV + (uint32_t)buf * (FA_VB * 2);
#pragma unroll
        for (int j = 0; j < 8; j++) {
            int t = tid + j * 256;
            int r = t >> 4, c8 = t & 15;
            cp16(kBase + (uint32_t)(r * FSTR + c8 * 8) * 2,
                 &krh[(size_t)(kb * 128 + r) * DD + c8 * 8]);
        }
#pragma unroll
        for (int j = 0; j < 8; j++) {
            int t = tid + j * 256;
            int d = t >> 4, j8 = t & 15;
            cp16(vBase + (uint32_t)(d * FSTR + j8 * 8) * 2,
                 &vrh[(size_t)d * SS + kb * 128 + j8 * 8]);
        }
    };

    // ---- load Q tile (prescaled, half) ----
    for (int t = tid; t < 128 * 32; t += 256) {
        int r = t >> 5, c4 = (t & 31) * 4;
        float4 v = *(const float4*)&qkv[((size_t)b * SS + qb * 128 + r) * QKV_W
                                        + h * DD + c4];
        __half2 h0 = __floats2half2_rn(v.x * scale, v.y * scale);
        __half2 h1 = __floats2half2_rn(v.z * scale, v.w * scale);
        uint2 o = { *(uint32_t*)&h0, *(uint32_t*)&h1 };
        *(uint2*)&Qs[r * FSTR + c4] = o;
    }

    issue_kv(0, 0);
    CP_COMMIT();
    __syncthreads();                      // Q tile visible

    // ---- hoist Q fragments (kv-invariant) ----
    uint32_t qf[8][4];
#pragma unroll
    for (int ks = 0; ks < 8; ks++)
        ldsm_x4(qf[ks], qFrag + ks * 32);

    float O[16][4];
#pragma unroll
    for (int nt = 0; nt < 16; nt++)
#pragma unroll
        for (int i = 0; i < 4; i++) O[nt][i] = 0.f;
    float m_lo = -INFINITY, m_hi = -INFINITY, l_lo = 0.f, l_hi = 0.f;

    const int nKV = qb + 1;                 // causal, 128-wide kv blocks

    for (int kb = 0; kb < nKV; kb++) {
        const int buf = kb & 1;
        CP_WAIT0();
        __syncthreads();   // stage kb visible; all reads of stage kb-1 done
        if (kb + 1 < nKV) {
            issue_kv(buf ^ 1, kb + 1);   // overlaps compute of stage kb
            CP_COMMIT();
        }

        const uint32_t kOff = (uint32_t)buf * (FA_KB * 2);
        const uint32_t vOff = (uint32_t)buf * (FA_VB * 2);

        // ---- S = Q K^T : m16 x n128 x k128 per warp (8 k16 steps) ----
        float S[16][4];
#pragma unroll
        for (int nt = 0; nt < 16; nt++)
#pragma unroll
            for (int i = 0; i < 4; i++) S[nt][i] = 0.f;
#pragma unroll
        for (int ks = 0; ks < 8; ks++) {
#pragma unroll
            for (int p = 0; p < 8; p++) {
                uint32_t r[4];
                ldsm_x4(r, kFrag + kOff + ks * 32 + p * (16 * FSTR * 2));
                mma_f16(S[2 * p], qf[ks], r);
                mma_f16(S[2 * p + 1], qf[ks], r + 2);
            }
        }

        // ---- diagonal block: add gmem mask ----
        if (kb == qb) {
            const int m_glo = qb * 128 + w * 16 + lr;
            const float* mr0 = &mask[((size_t)b * SS + m_glo) * SS + kb * 128];
            const float* mr1 = mr0 + 8 * SS;
#pragma unroll
            for (int nt = 0; nt < 16; nt++) {
                float2 q0 = *(const float2*)&mr0[nt * 8 + lc * 2];
                float2 q1 = *(const float2*)&mr1[nt * 8 + lc * 2];
                S[nt][0] += q0.x; S[nt][1] += q0.y;
                S[nt][2] += q1.x; S[nt][3] += q1.y;
            }
        }

        // ---- online softmax (rows lr and lr+8) ----
        float bm_lo = -INFINITY, bm_hi = -INFINITY;
#pragma unroll
        for (int nt = 0; nt < 16; nt++) {
            bm_lo = fmaxf(bm_lo, fmaxf(S[nt][0], S[nt][1]));
            bm_hi = fmaxf(bm_hi, fmaxf(S[nt][2], S[nt][3]));
        }
        bm_lo = fmaxf(bm_lo, __shfl_xor_sync(0xffffffff, bm_lo, 1));
        bm_lo = fmaxf(bm_lo, __shfl_xor_sync(0xffffffff, bm_lo, 2));
        bm_hi = fmaxf(bm_hi, __shfl_xor_sync(0xffffffff, bm_hi, 1));
        bm_hi = fmaxf(bm_hi, __shfl_xor_sync(0xffffffff, bm_hi, 2));
        float mn_lo = fmaxf(m_lo, bm_lo);
        float mn_hi = fmaxf(m_hi, bm_hi);

        float rs_lo = 0.f, rs_hi = 0.f;
#pragma unroll
        for (int nt = 0; nt < 16; nt++) {
            S[nt][0] = __expf(S[nt][0] - mn_lo);
            S[nt][1] = __expf(S[nt][1] - mn_lo);
            S[nt][2] = __expf(S[nt][2] - mn_hi);
            S[nt][3] = __expf(S[nt][3] - mn_hi);
            rs_lo += S[nt][0] + S[nt][1];
            rs_hi += S[nt][2] + S[nt][3];
        }
        rs_lo += __shfl_xor_sync(0xffffffff, rs_lo, 1);
        rs_lo += __shfl_xor_sync(0xffffffff, rs_lo, 2);
        rs_hi += __shfl_xor_sync(0xffffffff, rs_hi, 1);
        rs_hi += __shfl_xor_sync(0xffffffff, rs_hi, 2);

        float al_lo = __expf(m_lo - mn_lo);
        float al_hi = __expf(m_hi - mn_hi);
        l_lo = l_lo * al_lo + rs_lo;
        l_hi = l_hi * al_hi + rs_hi;
        m_lo = mn_lo; m_hi = mn_hi;
#pragma unroll
        for (int nt = 0; nt < 16; nt++) {
            O[nt][0] *= al_lo; O[nt][1] *= al_lo;
            O[nt][2] *= al_hi; O[nt][3] *= al_hi;
        }

        // ---- O += P V : P stays in registers (S-frag == A-frag layout) ----
#pragma unroll
        for (int ks = 0; ks < 8; ks++) {
            uint32_t af[4];
            af[0] = h2bits(__floats2half2_rn(S[2 * ks][0],     S[2 * ks][1]));
            af[1] = h2bits(__floats2half2_rn(S[2 * ks][2],     S[2 * ks][3]));
            af[2] = h2bits(__floats2half2_rn(S[2 * ks + 1][0], S[2 * ks + 1][1]));
            af[3] = h2bits(__floats2half2_rn(S[2 * ks + 1][2], S[2 * ks + 1][3]));
#pragma unroll
            for (int p = 0; p < 8; p++) {
                uint32_t r[4];
                ldsm_x4(r, vFrag + vOff + ks * 32 + p * (16 * FSTR * 2));
                mma_f16(O[2 * p], af, r);
                mma_f16(O[2 * p + 1], af, r + 2);
            }
        }
    }

    // epilogue: normalize, write half attn [B,S,H,D]
    const float inv_lo = 1.0f / l_lo, inv_hi = 1.0f / l_hi;
    const int m0 = qb * 128 + w * 16 + lr;
#pragma unroll
    for (int nt = 0; nt < 16; nt++) {
        int d = nt * 8 + lc * 2;
        __half2 v0 = __floats2half2_rn(O[nt][0] * inv_lo, O[nt][1] * inv_lo);
        __half2 v1 = __floats2half2_rn(O[nt][2] * inv_hi, O[nt][3] * inv_hi);
        *(__half2*)&attn_out[(((size_t)b * SS + m0) * HH + h) * DD + d] = v0;
        *(__half2*)&attn_out[(((size_t)b * SS + m0 + 8) * HH + h) * DD + d] = v1;
    }
}

// ---------------- launch ----------------------------------------------------
extern "C" void kernel_launch(void* const* d_in, const int* in_sizes, int n_in,
                              void* d_out, int out_size) {
    const float* x      = (const float*)d_in[0];
    const float* f_r    = (const float*)d_in[1];
    const float* f_i    = (const float*)d_in[2];
    const float* mask   = (const float*)d_in[3];
    const float* W_qkv  = (const float*)d_in[4];
    const float* b_qkv  = (const float*)d_in[5];
    const float* W_o    = (const float*)d_in[6];

    float* out   = (float*)d_out;
    float* out_k = out   + (size_t)BB * SS * NSTATE;
    float* out_v = out_k + (size_t)BB * SS * HH * DD;

    float* qkv = nullptr;    cudaGetSymbolAddress((void**)&qkv,   g_qkv);
    __half* attnh = nullptr; cudaGetSymbolAddress((void**)&attnh, g_attnh);
    __half* xh = nullptr;    cudaGetSymbolAddress((void**)&xh,    g_xh);
    __half* wqh = nullptr;   cudaGetSymbolAddress((void**)&wqh,   g_wqh);
    __half* woh = nullptr;   cudaGetSymbolAddress((void**)&woh,   g_woh);
    __half* kh = nullptr;    cudaGetSymbolAddress((void**)&kh,    g_kh);
    __half* vh = nullptr;    cudaGetSymbolAddress((void**)&vh,    g_vh);

    const int M = BB * SS;   // 4096

    cudaFuncSetAttribute(gemm_mma, cudaFuncAttributeMaxDynamicSharedMemorySize,
                         G_SMEM);
    cudaFuncSetAttribute(flash_attn, cudaFuncAttributeMaxDynamicSharedMemorySize,
                         FA_BYTES);

    // 0) pre-round GEMM inputs to fp16
    {
        int n4x = (M * NSTATE) / 4;
        round_half<<<(n4x + 255) / 256, 256>>>(x, xh, n4x);
        int n4q = (QKV_W * NSTATE) / 4;
        round_half<<<(n4q + 255) / 256, 256>>>(W_qkv, wqh, n4q);
        int n4o = (NSTATE * NSTATE) / 4;
        round_half<<<(n4o + 255) / 256, 256>>>(W_o, woh, n4o);
    }

    // 1) QKV projection (fp16 mma.sync, 64x64 warp tiles)
    gemm_mma<<<dim3(QKV_W / 128, M / 128), 128, G_SMEM>>>(
        xh, wqh, b_qkv, qkv, M, QKV_W, NSTATE);
    // 2) RoPE q,k; scatter k,v to output; k half head-major
    rope_scatter<<<(BB * SS * HH * 64) / 256, 256>>>(qkv, f_r, f_i,
                                                     out_k, out_v, kh);
    // 2b) V transpose to [B,H,D,S] half
    transpose_v<<<dim3(SS / 32, DD / 32, BB * HH), dim3(32, 8)>>>(out_v, vh);
    // 3) attention (fp16 mma, register P, hoisted Q, cp.async double-buffer)
    flash_attn<<<dim3(SS / 128, HH, BB), 256, FA_BYTES>>>(qkv, kh, vh,
                                                          mask, attnh);
    // 4) output projection (fp16 mma.sync, 64x64 warp tiles)
    gemm_mma<<<dim3(NSTATE / 128, M / 128), 128, G_SMEM>>>(
        attnh, woh, nullptr, out, M, NSTATE, NSTATE);
}

// round 13
// speedup vs baseline: 2.7459x; 1.0808x over previous
#include <cuda_runtime.h>
#include <cuda_fp16.h>
#include <cstdint>
#include <math.h>

// Problem constants
#define BB 2
#define SS 2048
#define HH 16
#define DD 128
#define NSTATE 2048
#define QKV_W (3*HH*DD)   // 6144

// ---------------- scratch (device globals; no runtime alloc) ----------------
__device__ float  g_qkv[(size_t)BB * SS * QKV_W];     // [B,S,6144] fp32
__device__ __half g_attnh[(size_t)BB * SS * HH * DD]; // attn out, half
__device__ __half g_xh[(size_t)BB * SS * NSTATE];     // x half
__device__ __half g_wqh[(size_t)QKV_W * NSTATE];      // W_qkv half
__device__ __half g_woh[(size_t)NSTATE * NSTATE];     // W_o half
__device__ __half g_qh[(size_t)BB * HH * SS * DD];    // q half prescaled [B,H,S,D]
__device__ __half g_kh[(size_t)BB * HH * SS * DD];    // k half [B,H,S,D]
__device__ __half g_vh[(size_t)BB * HH * SS * DD];    // v half [B,H,S,D]

// ---------------- helpers ----------------------------------------------------
__device__ __forceinline__ uint32_t smem_u32(const void* p) {
    uint32_t a;
    asm("{ .reg .u64 t; cvta.to.shared.u64 t, %1; cvt.u32.u64 %0, t; }"
        : "=r"(a) : "l"(p));
    return a;
}
__device__ __forceinline__ void mma_f16(float* c, const uint32_t* a,
                                        const uint32_t* b) {
    asm volatile(
        "mma.sync.aligned.m16n8k16.row.col.f32.f16.f16.f32 "
        "{%0,%1,%2,%3}, {%4,%5,%6,%7}, {%8,%9}, {%0,%1,%2,%3};\n"
        : "+f"(c[0]), "+f"(c[1]), "+f"(c[2]), "+f"(c[3])
        : "r"(a[0]), "r"(a[1]), "r"(a[2]), "r"(a[3]), "r"(b[0]), "r"(b[1]));
}
__device__ __forceinline__ void ldsm_x4(uint32_t* r, uint32_t addr) {
    asm volatile("ldmatrix.sync.aligned.m8n8.x4.shared.b16 {%0,%1,%2,%3}, [%4];"
                 : "=r"(r[0]), "=r"(r[1]), "=r"(r[2]), "=r"(r[3]) : "r"(addr));
}
__device__ __forceinline__ void ldsm_x4_t(uint32_t* r, uint32_t addr) {
    asm volatile("ldmatrix.sync.aligned.m8n8.x4.trans.shared.b16 {%0,%1,%2,%3}, [%4];"
                 : "=r"(r[0]), "=r"(r[1]), "=r"(r[2]), "=r"(r[3]) : "r"(addr));
}
__device__ __forceinline__ void cp16(uint32_t s, const void* g) {
    asm volatile("cp.async.cg.shared.global [%0], [%1], 16;"
                 :: "r"(s), "l"(g) : "memory");
}
__device__ __forceinline__ uint32_t h2bits(__half2 h) {
    return *(uint32_t*)&h;
}
#define CP_COMMIT() asm volatile("cp.async.commit_group;" ::: "memory")
#define CP_WAIT2()  asm volatile("cp.async.wait_group 2;"  ::: "memory")
#define CP_WAIT0()  asm volatile("cp.async.wait_group 0;"  ::: "memory")

// ---------------- fp32 -> fp16 pre-round pass --------------------------------
__global__ void round_half(const float* __restrict__ src,
                           __half* __restrict__ dst, int n4) {
    int i = blockIdx.x * blockDim.x + threadIdx.x;
    if (i >= n4) return;
    float4 v = ((const float4*)src)[i];
    __half2 h0 = __floats2half2_rn(v.x, v.y);
    __half2 h1 = __floats2half2_rn(v.z, v.w);
    uint2 o = { *(uint32_t*)&h0, *(uint32_t*)&h1 };
    ((uint2*)dst)[i] = o;
}

// ============================================================================
// fp16 mma.sync GEMM (NT): C[m,n] = sum_k A[m,k]*B[n,k] (+bias[n]), fp32 acc
// Block 128x128, BK=32 halves, 4 warps (2x2), warp tile 64x64,
// 4-stage cp.async ring, TPH=40 rows, ldmatrix. 2 CTAs/SM (128 thr each).
// ============================================================================
#define TPH 40                                // halves; 80B row (5x16B, odd)
#define G_NSTG 4
#define G_AB (128 * TPH * 2)                  // 10240 B per operand tile
#define G_STG (2 * G_AB)                      // 20480 B per stage
#define G_SMEM (G_NSTG * G_STG)               // 81920 B

__device__ __forceinline__ void gemm_issue(uint32_t sbase,
                                           const __half* __restrict__ A,
                                           const __half* __restrict__ B,
                                           int m0, int n0, int K, int k0,
                                           int tid) {
#pragma unroll
    for (int j = 0; j < 4; j++) {               // 512 chunks of A
        int t = tid + j * 128;
        int row = t >> 2, seg = t & 3;
        cp16(sbase + (uint32_t)(row * TPH + seg * 8) * 2,
             &A[(size_t)(m0 + row) * K + k0 + seg * 8]);
    }
    const uint32_t sB = sbase + G_AB;
#pragma unroll
    for (int j = 0; j < 4; j++) {               // 512 chunks of B
        int t = tid + j * 128;
        int row = t >> 2, seg = t & 3;
        cp16(sB + (uint32_t)(row * TPH + seg * 8) * 2,
             &B[(size_t)(n0 + row) * K + k0 + seg * 8]);
    }
}

__global__ __launch_bounds__(128, 2)
void gemm_mma(const __half* __restrict__ A, const __half* __restrict__ B,
              const float* __restrict__ bias, float* __restrict__ C,
              int M, int N, int K) {
    extern __shared__ uint32_t dynsm[];
    const uint32_t sb = smem_u32(dynsm);

    const int tid = threadIdx.x;
    const int w = tid >> 5, l = tid & 31;
    const int lr = l >> 2, lc = l & 3;
    const int wm = w >> 1, wn = w & 1;           // 2 (m) x 2 (n)
    const int m0 = blockIdx.y * 128, n0 = blockIdx.x * 128;
    const int mat = l >> 3;

    const uint32_t aOff = (uint32_t)(((wm * 64 + (mat & 1) * 8 + (l & 7)) * TPH)
                                     + (mat >> 1) * 8) * 2;
    const uint32_t bOff = G_AB
                        + (uint32_t)(((wn * 64 + (mat >> 1) * 8 + (l & 7)) * TPH)
                                     + (mat & 1) * 8) * 2;

    float acc[4][8][4];
#pragma unroll
    for (int mt = 0; mt < 4; mt++)
#pragma unroll
        for (int nt = 0; nt < 8; nt++)
#pragma unroll
            for (int i = 0; i < 4; i++) acc[mt][nt][i] = 0.f;

    const int NC = K / 32;

#pragma unroll
    for (int s = 0; s < G_NSTG - 1; s++) {
        gemm_issue(sb + s * G_STG, A, B, m0, n0, K, s * 32, tid);
        CP_COMMIT();
    }

    for (int c = 0; c < NC; c++) {
        CP_WAIT2();
        __syncthreads();

        const int nc = c + G_NSTG - 1;
        if (nc < NC)
            gemm_issue(sb + (nc % G_NSTG) * G_STG, A, B, m0, n0, K, nc * 32, tid);
        CP_COMMIT();

        const uint32_t st = sb + (c % G_NSTG) * G_STG;
#pragma unroll
        for (int kk = 0; kk < 2; kk++) {
            uint32_t af[4][4];
#pragma unroll
            for (int mt = 0; mt < 4; mt++)
                ldsm_x4(af[mt], st + aOff + kk * 32 + mt * (16 * TPH * 2));
#pragma unroll
            for (int p = 0; p < 4; p++) {
                uint32_t r[4];
                ldsm_x4(r, st + bOff + kk * 32 + p * (16 * TPH * 2));
#pragma unroll
                for (int mt = 0; mt < 4; mt++) {
                    mma_f16(acc[mt][2 * p],     af[mt], r);
                    mma_f16(acc[mt][2 * p + 1], af[mt], r + 2);
                }
            }
        }
    }

#pragma unroll
    for (int mt = 0; mt < 4; mt++) {
        int m = m0 + wm * 64 + mt * 16 + lr;
#pragma unroll
        for (int nt = 0; nt < 8; nt++) {
            int n = n0 + wn * 64 + nt * 8 + lc * 2;
            float bx = 0.f, by = 0.f;
            if (bias) { bx = bias[n]; by = bias[n + 1]; }
            float2 v0 = { acc[mt][nt][0] + bx, acc[mt][nt][1] + by };
            float2 v1 = { acc[mt][nt][2] + bx, acc[mt][nt][3] + by };
            *(float2*)&C[(size_t)m * N + n] = v0;
            *(float2*)&C[(size_t)(m + 8) * N + n] = v1;
        }
    }
}

// ---------------- RoPE: q -> g_qh (half, prescaled, head-major);
//                  k -> out_k (fp32) + g_kh; v -> out_v (fp32) + g_vh --------
__global__ void rope_scatter(const float* __restrict__ qkv,
                             const float* __restrict__ f_r,
                             const float* __restrict__ f_i,
                             float* __restrict__ out_k,
                             float* __restrict__ out_v,
                             __half* __restrict__ qh,
                             __half* __restrict__ kh,
                             __half* __restrict__ vh) {
    int idx = blockIdx.x * blockDim.x + threadIdx.x;
    if (idx >= BB * SS * HH * 64) return;
    int d2 = idx & 63;
    int h  = (idx >> 6) & (HH - 1);
    int bs = idx >> 10;
    int b = bs >> 11, s = bs & (SS - 1);
    const float scale = 0.08838834764831845f;   // 1/sqrt(128)

    float fr = f_r[(size_t)bs * 64 + d2];
    float fi = f_i[(size_t)bs * 64 + d2];

    size_t base = (size_t)bs * QKV_W;
    size_t hmaj = (((size_t)(b * HH + h) * SS) + s) * DD + d2;

    // q: rope, prescale, half (head-major)
    size_t qi = base + (size_t)h * DD + d2;
    float xr = qkv[qi], xi = qkv[qi + 64];
    qh[hmaj]      = __float2half_rn((xr * fr - xi * fi) * scale);
    qh[hmaj + 64] = __float2half_rn((xr * fi + xi * fr) * scale);

    // k: rope -> fp32 output + half head-major
    size_t ki = base + (size_t)HH * DD + (size_t)h * DD + d2;
    xr = qkv[ki]; xi = qkv[ki + 64];
    float klo = xr * fr - xi * fi;
    float khi = xr * fi + xi * fr;
    size_t ko = ((size_t)bs * HH + h) * DD + d2;
    out_k[ko]      = klo;
    out_k[ko + 64] = khi;
    kh[hmaj]      = __float2half_rn(klo);
    kh[hmaj + 64] = __float2half_rn(khi);

    // v: copy -> fp32 output + half head-major
    size_t vi = base + (size_t)2 * HH * DD + (size_t)h * DD + d2;
    float vlo = qkv[vi], vhi = qkv[vi + 64];
    out_v[ko]      = vlo;
    out_v[ko + 64] = vhi;
    vh[hmaj]      = __float2half_rn(vlo);
    vh[hmaj + 64] = __float2half_rn(vhi);
}

// ============================================================================
// Flash attention, fp16 mma.sync + ldmatrix(+trans for V) + cp.async.
// BM=128 (8 warps x 16), BN=128. Q/K/V all half head-major [B,H,S,D].
// Q fragments hoisted; P register-resident. Causal; heavy tiles first.
// ============================================================================
#define FSTR 136   // halves: row stride (272B, odd 16B count)
#define FA_KB   (128 * FSTR)             // K stage, halves
#define FA_VB   (128 * FSTR)             // V stage, halves
#define FA_BYTES ((128*FSTR /*Q*/ + 2*FA_KB + 2*FA_VB) * 2)   // 174080 B

__global__ __launch_bounds__(256, 1)
void flash_attn(const __half* __restrict__ qh,
                const __half* __restrict__ kh,
                const __half* __restrict__ vh,
                const float* __restrict__ mask,
                __half* __restrict__ attn_out) {
    extern __shared__ __half smh[];
    __half* Qs  = smh;                    // [128][FSTR]
    __half* Ks0 = Qs + 128 * FSTR;        // [2][128][FSTR]  rows = kv pos
    __half* Vs0 = Ks0 + 2 * FA_KB;        // [2][128][FSTR]  rows = kv pos

    // heavy (large-qb) tiles first for better makespan
    const int qb = (int)gridDim.x - 1 - (int)blockIdx.x;
    const int h = blockIdx.y, b = blockIdx.z;
    const int tid = threadIdx.x, w = tid >> 5, l = tid & 31;
    const int lr = l >> 2, lc = l & 3;

    const int mat = l >> 3;
    const uint32_t sQ = smem_u32(Qs), sK = smem_u32(Ks0);
    const uint32_t sV = smem_u32(Vs0);
    const uint32_t qFrag = sQ + (uint32_t)(((w * 16 + (mat & 1) * 8 + (l & 7)) * FSTR)
                                           + (mat >> 1) * 8) * 2;
    const uint32_t kFrag = sK + (uint32_t)((((mat >> 1) * 8 + (l & 7)) * FSTR)
                                           + (mat & 1) * 8) * 2;
    // V (trans): row = k-position within k16 group, col = d offset
    const uint32_t vFrag = sV + (uint32_t)((((mat & 1) * 8 + (l & 7)) * FSTR)
                                           + (mat >> 1) * 8) * 2;

    const __half* qrh = qh + ((size_t)(b * HH + h) * SS) * DD;
    const __half* krh = kh + ((size_t)(b * HH + h) * SS) * DD;
    const __half* vrh = vh + ((size_t)(b * HH + h) * SS) * DD;

    // ---- K/V stage issue via cp.async (16 cp16 per thread) ----
    auto issue_kv = [&](int buf, int kb) {
        const uint32_t kBase = sK + (uint32_t)buf * (FA_KB * 2);
        const uint32_t vBase = sV + (uint32_t)buf * (FA_VB * 2);
#pragma unroll
        for (int j = 0; j < 8; j++) {
            int t = tid + j * 256;
            int r = t >> 4, c8 = t & 15;
            cp16(kBase + (uint32_t)(r * FSTR + c8 * 8) * 2,
                 &krh[(size_t)(kb * 128 + r) * DD + c8 * 8]);
        }
#pragma unroll
        for (int j = 0; j < 8; j++) {
            int t = tid + j * 256;
            int r = t >> 4, c8 = t & 15;
            cp16(vBase + (uint32_t)(r * FSTR + c8 * 8) * 2,
                 &vrh[(size_t)(kb * 128 + r) * DD + c8 * 8]);
        }
    };

    // ---- Q tile via cp.async (already prescaled half) ----
#pragma unroll
    for (int j = 0; j < 8; j++) {
        int t = tid + j * 256;
        int r = t >> 4, c8 = t & 15;
        cp16(sQ + (uint32_t)(r * FSTR + c8 * 8) * 2,
             &qrh[(size_t)(qb * 128 + r) * DD + c8 * 8]);
    }
    CP_COMMIT();
    issue_kv(0, 0);
    CP_COMMIT();
    CP_WAIT0();
    __syncthreads();                      // Q + stage 0 visible

    // ---- hoist Q fragments (kv-invariant) ----
    uint32_t qf[8][4];
#pragma unroll
    for (int ks = 0; ks < 8; ks++)
        ldsm_x4(qf[ks], qFrag + ks * 32);

    float O[16][4];
#pragma unroll
    for (int nt = 0; nt < 16; nt++)
#pragma unroll
        for (int i = 0; i < 4; i++) O[nt][i] = 0.f;
    float m_lo = -INFINITY, m_hi = -INFINITY, l_lo = 0.f, l_hi = 0.f;

    const int nKV = qb + 1;                 // causal, 128-wide kv blocks

    for (int kb = 0; kb < nKV; kb++) {
        const int buf = kb & 1;
        if (kb > 0) {
            CP_WAIT0();
            __syncthreads();   // stage kb visible; reads of stage kb-1 done
        }
        if (kb + 1 < nKV) {
            issue_kv(buf ^ 1, kb + 1);   // overlaps compute of stage kb
            CP_COMMIT();
        }

        const uint32_t kOff = (uint32_t)buf * (FA_KB * 2);
        const uint32_t vOff = (uint32_t)buf * (FA_VB * 2);

        // ---- S = Q K^T : m16 x n128 x k128 per warp (8 k16 steps) ----
        float S[16][4];
#pragma unroll
        for (int nt = 0; nt < 16; nt++)
#pragma unroll
            for (int i = 0; i < 4; i++) S[nt][i] = 0.f;
#pragma unroll
        for (int ks = 0; ks < 8; ks++) {
#pragma unroll
            for (int p = 0; p < 8; p++) {
                uint32_t r[4];
                ldsm_x4(r, kFrag + kOff + ks * 32 + p * (16 * FSTR * 2));
                mma_f16(S[2 * p], qf[ks], r);
                mma_f16(S[2 * p + 1], qf[ks], r + 2);
            }
        }

        // ---- diagonal block: add gmem mask ----
        if (kb == qb) {
            const int m_glo = qb * 128 + w * 16 + lr;
            const float* mr0 = &mask[((size_t)b * SS + m_glo) * SS + kb * 128];
            const float* mr1 = mr0 + 8 * SS;
#pragma unroll
            for (int nt = 0; nt < 16; nt++) {
                float2 q0 = *(const float2*)&mr0[nt * 8 + lc * 2];
                float2 q1 = *(const float2*)&mr1[nt * 8 + lc * 2];
                S[nt][0] += q0.x; S[nt][1] += q0.y;
                S[nt][2] += q1.x; S[nt][3] += q1.y;
            }
        }

        // ---- online softmax (rows lr and lr+8) ----
        float bm_lo = -INFINITY, bm_hi = -INFINITY;
#pragma unroll
        for (int nt = 0; nt < 16; nt++) {
            bm_lo = fmaxf(bm_lo, fmaxf(S[nt][0], S[nt][1]));
            bm_hi = fmaxf(bm_hi, fmaxf(S[nt][2], S[nt][3]));
        }
        bm_lo = fmaxf(bm_lo, __shfl_xor_sync(0xffffffff, bm_lo, 1));
        bm_lo = fmaxf(bm_lo, __shfl_xor_sync(0xffffffff, bm_lo, 2));
        bm_hi = fmaxf(bm_hi, __shfl_xor_sync(0xffffffff, bm_hi, 1));
        bm_hi = fmaxf(bm_hi, __shfl_xor_sync(0xffffffff, bm_hi, 2));
        float mn_lo = fmaxf(m_lo, bm_lo);
        float mn_hi = fmaxf(m_hi, bm_hi);

        float rs_lo = 0.f, rs_hi = 0.f;
#pragma unroll
        for (int nt = 0; nt < 16; nt++) {
            S[nt][0] = __expf(S[nt][0] - mn_lo);
            S[nt][1] = __expf(S[nt][1] - mn_lo);
            S[nt][2] = __expf(S[nt][2] - mn_hi);
            S[nt][3] = __expf(S[nt][3] - mn_hi);
            rs_lo += S[nt][0] + S[nt][1];
            rs_hi += S[nt][2] + S[nt][3];
        }
        rs_lo += __shfl_xor_sync(0xffffffff, rs_lo, 1);
        rs_lo += __shfl_xor_sync(0xffffffff, rs_lo, 2);
        rs_hi += __shfl_xor_sync(0xffffffff, rs_hi, 1);
        rs_hi += __shfl_xor_sync(0xffffffff, rs_hi, 2);

        float al_lo = __expf(m_lo - mn_lo);
        float al_hi = __expf(m_hi - mn_hi);
        l_lo = l_lo * al_lo + rs_lo;
        l_hi = l_hi * al_hi + rs_hi;
        m_lo = mn_lo; m_hi = mn_hi;
#pragma unroll
        for (int nt = 0; nt < 16; nt++) {
            O[nt][0] *= al_lo; O[nt][1] *= al_lo;
            O[nt][2] *= al_hi; O[nt][3] *= al_hi;
        }

        // ---- O += P V : P register-resident; V via ldmatrix.trans ----
#pragma unroll
        for (int ks = 0; ks < 8; ks++) {
            uint32_t af[4];
            af[0] = h2bits(__floats2half2_rn(S[2 * ks][0],     S[2 * ks][1]));
            af[1] = h2bits(__floats2half2_rn(S[2 * ks][2],     S[2 * ks][3]));
            af[2] = h2bits(__floats2half2_rn(S[2 * ks + 1][0], S[2 * ks + 1][1]));
            af[3] = h2bits(__floats2half2_rn(S[2 * ks + 1][2], S[2 * ks + 1][3]));
#pragma unroll
            for (int p = 0; p < 8; p++) {
                uint32_t r[4];
                ldsm_x4_t(r, vFrag + vOff + ks * (16 * FSTR * 2) + p * 32);
                mma_f16(O[2 * p], af, r);
                mma_f16(O[2 * p + 1], af, r + 2);
            }
        }
    }

    // epilogue: normalize, write half attn [B,S,H,D]
    const float inv_lo = 1.0f / l_lo, inv_hi = 1.0f / l_hi;
    const int m0 = qb * 128 + w * 16 + lr;
#pragma unroll
    for (int nt = 0; nt < 16; nt++) {
        int d = nt * 8 + lc * 2;
        __half2 v0 = __floats2half2_rn(O[nt][0] * inv_lo, O[nt][1] * inv_lo);
        __half2 v1 = __floats2half2_rn(O[nt][2] * inv_hi, O[nt][3] * inv_hi);
        *(__half2*)&attn_out[(((size_t)b * SS + m0) * HH + h) * DD + d] = v0;
        *(__half2*)&attn_out[(((size_t)b * SS + m0 + 8) * HH + h) * DD + d] = v1;
    }
}

// ---------------- launch ----------------------------------------------------
extern "C" void kernel_launch(void* const* d_in, const int* in_sizes, int n_in,
                              void* d_out, int out_size) {
    const float* x      = (const float*)d_in[0];
    const float* f_r    = (const float*)d_in[1];
    const float* f_i    = (const float*)d_in[2];
    const float* mask   = (const float*)d_in[3];
    const float* W_qkv  = (const float*)d_in[4];
    const float* b_qkv  = (const float*)d_in[5];
    const float* W_o    = (const float*)d_in[6];

    float* out   = (float*)d_out;
    float* out_k = out   + (size_t)BB * SS * NSTATE;
    float* out_v = out_k + (size_t)BB * SS * HH * DD;

    float* qkv = nullptr;    cudaGetSymbolAddress((void**)&qkv,   g_qkv);
    __half* attnh = nullptr; cudaGetSymbolAddress((void**)&attnh, g_attnh);
    __half* xh = nullptr;    cudaGetSymbolAddress((void**)&xh,    g_xh);
    __half* wqh = nullptr;   cudaGetSymbolAddress((void**)&wqh,   g_wqh);
    __half* woh = nullptr;   cudaGetSymbolAddress((void**)&woh,   g_woh);
    __half* qh = nullptr;    cudaGetSymbolAddress((void**)&qh,    g_qh);
    __half* kh = nullptr;    cudaGetSymbolAddress((void**)&kh,    g_kh);
    __half* vh = nullptr;    cudaGetSymbolAddress((void**)&vh,    g_vh);

    const int M = BB * SS;   // 4096

    cudaFuncSetAttribute(gemm_mma, cudaFuncAttributeMaxDynamicSharedMemorySize,
                         G_SMEM);
    cudaFuncSetAttribute(flash_attn, cudaFuncAttributeMaxDynamicSharedMemorySize,
                         FA_BYTES);

    // 0) pre-round GEMM inputs to fp16
    {
        int n4x = (M * NSTATE) / 4;
        round_half<<<(n4x + 255) / 256, 256>>>(x, xh, n4x);
        int n4q = (QKV_W * NSTATE) / 4;
        round_half<<<(n4q + 255) / 256, 256>>>(W_qkv, wqh, n4q);
        int n4o = (NSTATE * NSTATE) / 4;
        round_half<<<(n4o + 255) / 256, 256>>>(W_o, woh, n4o);
    }

    // 1) QKV projection (fp16 mma.sync, 64x64 warp tiles)
    gemm_mma<<<dim3(QKV_W / 128, M / 128), 128, G_SMEM>>>(
        xh, wqh, b_qkv, qkv, M, QKV_W, NSTATE);
    // 2) RoPE: q/k/v -> half head-major + fp32 k,v outputs
    rope_scatter<<<(BB * SS * HH * 64) / 256, 256>>>(qkv, f_r, f_i,
                                                     out_k, out_v, qh, kh, vh);
    // 3) attention (fp16 mma, trans-ldmatrix V, register P, cp.async)
    flash_attn<<<dim3(SS / 128, HH, BB), 256, FA_BYTES>>>(qh, kh, vh,
                                                          mask, attnh);
    // 4) output projection (fp16 mma.sync, 64x64 warp tiles)
    gemm_mma<<<dim3(NSTATE / 128, M / 128), 128, G_SMEM>>>(
        attnh, woh, nullptr, out, M, NSTATE, NSTATE);
}